// round 5
// baseline (speedup 1.0000x reference)
#include <cuda_runtime.h>
#include <cuda_bf16.h>

#define NNODE   100000
#define NEDGE   3200000
#define DIM     300
#define HID     16
#define NG      5
#define TOT     (NG*NNODE)      // 500000
#define TOTEDGE (NG*NEDGE)      // 16000000
#define CAP     80              // bucket slots per node; P(deg>=80)~5e-13 per node

// -------- scratch (no allocations allowed; __device__ globals) --------
__device__ __align__(16) float          g_scr[TOT*HID];   // raw emb@W1 (fp32)
__device__ __align__(16) unsigned short gb_scr[TOT*HID];  // scaled bf16 g (16MB)
__device__ int   bucket_scr[TOT*CAP];                     // 160MB: src lists by dst
__device__ int   cnt_scr[TOT];                            // in-degree
__device__ float dis_scr[TOT];
__device__ float f_scr[TOT];                              // f[n] = z[n]*dis[n]
__device__ float score_scr[NG];

// -------- f32x2 helpers --------
__device__ __forceinline__ unsigned long long fma_f32x2(unsigned long long a,
                                                        unsigned long long b,
                                                        unsigned long long c) {
    unsigned long long d;
    asm("fma.rn.f32x2 %0, %1, %2, %3;" : "=l"(d) : "l"(a), "l"(b), "l"(c));
    return d;
}
__device__ __forceinline__ unsigned long long pack_f32x2(float lo, float hi) {
    unsigned long long r;
    asm("mov.b64 %0, {%1, %2};" : "=l"(r) : "f"(lo), "f"(hi));
    return r;
}
__device__ __forceinline__ void unpack_f32x2(unsigned long long v, float& lo, float& hi) {
    asm("mov.b64 {%0, %1}, %2;" : "=f"(lo), "=f"(hi) : "l"(v));
}
__device__ __forceinline__ unsigned bf2pack(float a, float b) {
    __nv_bfloat162 t = __float22bfloat162_rn(make_float2(a, b));
    return *(unsigned*)&t;
}

// -------- bucket fill: per-block dtype detect, one atomic per edge --------
__global__ void fill_kernel(const void* __restrict__ ei) {
    __shared__ int s64;
    if (threadIdx.x < 32) {
        const unsigned long long* p = (const unsigned long long*)ei;
        unsigned long long a = p[threadIdx.x];
        unsigned long long b = p[threadIdx.x + 32];
        int bad = ((a >> 32) | (b >> 32)) != 0ULL;   // int32 data -> high words nonzero w.h.p.
        unsigned m = __ballot_sync(0xffffffffu, bad);
        if (threadIdx.x == 0) s64 = (m == 0);
    }
    __syncthreads();
    int is64 = s64;

    int e0 = (blockIdx.x * blockDim.x + threadIdx.x) * 4;
    if (e0 >= NEDGE) return;
    int gy = blockIdx.y;
    int nb = gy * NNODE;
    int s[4], d[4];
    if (is64) {
        const long long* base = (const long long*)ei + (long long)gy * 2 * NEDGE;
        longlong2 sa = *(const longlong2*)(base + e0);
        longlong2 sb = *(const longlong2*)(base + e0 + 2);
        longlong2 da = *(const longlong2*)(base + NEDGE + e0);
        longlong2 db = *(const longlong2*)(base + NEDGE + e0 + 2);
        s[0]=(int)sa.x; s[1]=(int)sa.y; s[2]=(int)sb.x; s[3]=(int)sb.y;
        d[0]=(int)da.x; d[1]=(int)da.y; d[2]=(int)db.x; d[3]=(int)db.y;
    } else {
        const int* base = (const int*)ei + (long long)gy * 2 * NEDGE;
        int4 sv = *(const int4*)(base + e0);
        int4 dv = *(const int4*)(base + NEDGE + e0);
        s[0]=sv.x; s[1]=sv.y; s[2]=sv.z; s[3]=sv.w;
        d[0]=dv.x; d[1]=dv.y; d[2]=dv.z; d[3]=dv.w;
    }
    #pragma unroll
    for (int r = 0; r < 4; ++r) {
        int ds = nb + d[r];
        int pos = atomicAdd(&cnt_scr[ds], 1);
        if (pos < CAP) bucket_scr[ds * CAP + pos] = nb + s[r];
    }
}

// -------- GEMM (raw fp32, f32x2 packed FMA, 2 nodes/thread) --------
#define JC 30
#define SA_STRIDE 513
#define SWD_ULL   (DIM*HID)                      // 4800 packed (w,w) entries, 38400B
#define SA_FLOATS (JC*SA_STRIDE)                 // 15390
#define GEMM_SMEM (SWD_ULL*8 + SA_FLOATS*4)      // 99960B

__global__ void __launch_bounds__(256) gemm_kernel(const float* __restrict__ emb,
                                                   const float* __restrict__ W1) {
    extern __shared__ char smraw[];
    unsigned long long* sWd = (unsigned long long*)smraw;           // 4800 × 8B
    float* sA = (float*)(smraw + SWD_ULL * 8);                      // [JC][513]
    int tid = threadIdx.x;
    int nbase = blockIdx.x * 512;

    for (int idx = tid; idx < SWD_ULL; idx += 256) {
        float w = W1[idx];
        sWd[idx] = pack_f32x2(w, w);
    }

    unsigned long long accp[16];
    #pragma unroll
    for (int k = 0; k < 16; ++k) accp[k] = 0ULL;   // (0.0f, 0.0f)

    for (int c = 0; c < 10; ++c) {
        int j0 = c * JC;
        __syncthreads();
        #pragma unroll
        for (int it = 0; it < 30; ++it) {
            int idx = it * 256 + tid;
            int n = idx / 15;
            int jp = idx - n * 15;
            int gn = nbase + n;
            float2 v = make_float2(0.f, 0.f);
            if (gn < TOT)
                v = *(const float2*)(emb + (size_t)gn * DIM + j0 + 2 * jp);
            sA[(2 * jp)     * SA_STRIDE + n] = v.x;
            sA[(2 * jp + 1) * SA_STRIDE + n] = v.y;
        }
        __syncthreads();
        #pragma unroll
        for (int jl = 0; jl < JC; ++jl) {
            float a0 = sA[jl * SA_STRIDE + tid];
            float a1 = sA[jl * SA_STRIDE + 256 + tid];
            unsigned long long ap = pack_f32x2(a0, a1);
            const ulonglong2* wr = (const ulonglong2*)(sWd + (j0 + jl) * HID);
            #pragma unroll
            for (int t = 0; t < 8; ++t) {
                ulonglong2 w2 = wr[t];
                accp[2*t]   = fma_f32x2(ap, w2.x, accp[2*t]);
                accp[2*t+1] = fma_f32x2(ap, w2.y, accp[2*t+1]);
            }
        }
    }

    float v0[16], v1[16];
    #pragma unroll
    for (int k = 0; k < 16; ++k) unpack_f32x2(accp[k], v0[k], v1[k]);

    int gn0 = nbase + tid;
    int gn1 = nbase + 256 + tid;
    if (gn0 < TOT) {
        float4* o = (float4*)(g_scr + (size_t)gn0 * HID);
        o[0] = make_float4(v0[0],  v0[1],  v0[2],  v0[3]);
        o[1] = make_float4(v0[4],  v0[5],  v0[6],  v0[7]);
        o[2] = make_float4(v0[8],  v0[9],  v0[10], v0[11]);
        o[3] = make_float4(v0[12], v0[13], v0[14], v0[15]);
    }
    if (gn1 < TOT) {
        float4* o = (float4*)(g_scr + (size_t)gn1 * HID);
        o[0] = make_float4(v1[0],  v1[1],  v1[2],  v1[3]);
        o[1] = make_float4(v1[4],  v1[5],  v1[6],  v1[7]);
        o[2] = make_float4(v1[8],  v1[9],  v1[10], v1[11]);
        o[3] = make_float4(v1[12], v1[13], v1[14], v1[15]);
    }
}

// -------- fused: dis = rsqrt(deg+1); gb = bf16(g * dis) (thread per node) --------
__global__ void disscale_kernel() {
    int n = blockIdx.x * blockDim.x + threadIdx.x;
    if (n >= TOT) return;
    float dd = rsqrtf((float)cnt_scr[n] + 1.0f);
    dis_scr[n] = dd;
    const float4* gi = (const float4*)(g_scr + (size_t)n * HID);
    float4 a = gi[0], b = gi[1], c = gi[2], d = gi[3];
    uint4 o0, o1;
    o0.x = bf2pack(a.x*dd, a.y*dd);  o0.y = bf2pack(a.z*dd, a.w*dd);
    o0.z = bf2pack(b.x*dd, b.y*dd);  o0.w = bf2pack(b.z*dd, b.w*dd);
    o1.x = bf2pack(c.x*dd, c.y*dd);  o1.y = bf2pack(c.z*dd, c.w*dd);
    o1.z = bf2pack(d.x*dd, d.y*dd);  o1.w = bf2pack(d.z*dd, d.w*dd);
    uint4* go = (uint4*)(gb_scr + (size_t)n * HID);
    go[0] = o0; go[1] = o1;
}

// -------- gather + layer1 + layer2 dot; stores f[n], accumulates self term --------
// warp per node; lane = (edge-slot 0..7) x (quarter 0..3); 8 edges per warp step; bf16 rows.
__global__ void __launch_bounds__(256) gather_kernel(const float* __restrict__ b1,
                                                     const float* __restrict__ W2) {
    int wid  = threadIdx.x >> 5;
    int lane = threadIdx.x & 31;
    int n = blockIdx.x * 8 + wid;            // 100000 % 8 == 0: blocks never straddle graphs
    int gidx = blockIdx.x / (NNODE / 8);

    int cnt = cnt_scr[n];
    if (cnt > CAP) cnt = CAP;
    int start = n * CAP;
    int q = lane & 3;                        // quarter (4 k-dims = 8 bytes bf16)
    int es = lane >> 2;                      // edge slot within group of 8

    float4 acc = make_float4(0.f, 0.f, 0.f, 0.f);
    const uint2* gbp = (const uint2*)gb_scr; // row n = 4 × uint2

    for (int base = 0; base < cnt; base += 32) {
        int rem = cnt - base;
        int m = rem < 32 ? rem : 32;
        int sv = (lane < m) ? bucket_scr[start + base + lane] : 0;
        if (m == 32) {
            #pragma unroll
            for (int j = 0; j < 4; ++j) {
                int s = __shfl_sync(0xffffffffu, sv, j * 8 + es);
                uint2 v = gbp[s * 4 + q];
                float2 p0 = __bfloat1622float2(*(__nv_bfloat162*)&v.x);
                float2 p1 = __bfloat1622float2(*(__nv_bfloat162*)&v.y);
                acc.x += p0.x; acc.y += p0.y; acc.z += p1.x; acc.w += p1.y;
            }
        } else {
            #pragma unroll
            for (int j = 0; j < 4; ++j) {
                int e = j * 8 + es;
                int s = __shfl_sync(0xffffffffu, sv, e);
                if (e < m) {
                    uint2 v = gbp[s * 4 + q];
                    float2 p0 = __bfloat1622float2(*(__nv_bfloat162*)&v.x);
                    float2 p1 = __bfloat1622float2(*(__nv_bfloat162*)&v.y);
                    acc.x += p0.x; acc.y += p0.y; acc.z += p1.x; acc.w += p1.y;
                }
            }
        }
    }
    // reduce 8 edge-slots -> lanes 0..3 (same quarter)
    #pragma unroll
    for (int off = 16; off >= 4; off >>= 1) {
        acc.x += __shfl_down_sync(0xffffffffu, acc.x, off);
        acc.y += __shfl_down_sync(0xffffffffu, acc.y, off);
        acc.z += __shfl_down_sync(0xffffffffu, acc.z, off);
        acc.w += __shfl_down_sync(0xffffffffu, acc.w, off);
    }

    float dd = dis_scr[n];
    float zp = 0.f;
    if (lane < 4) {
        uint2 gv = gbp[n * 4 + q];
        float2 g0 = __bfloat1622float2(*(__nv_bfloat162*)&gv.x);
        float2 g1 = __bfloat1622float2(*(__nv_bfloat162*)&gv.y);
        float4 bb = __ldg((const float4*)b1 + q);
        float4 ww = __ldg((const float4*)W2 + q);
        float h0 = fmaxf(fmaf(dd, acc.x + g0.x, bb.x), 0.f);
        float h1 = fmaxf(fmaf(dd, acc.y + g0.y, bb.y), 0.f);
        float h2 = fmaxf(fmaf(dd, acc.z + g1.x, bb.z), 0.f);
        float h3 = fmaxf(fmaf(dd, acc.w + g1.y, bb.w), 0.f);
        zp = h0 * ww.x + h1 * ww.y + h2 * ww.z + h3 * ww.w;
    }
    zp += __shfl_down_sync(0xffffffffu, zp, 2);
    zp += __shfl_down_sync(0xffffffffu, zp, 1);

    __shared__ float part[8];
    if (lane == 0) {
        float f = zp * dd;                   // f[n] = z[n]*dis[n]
        f_scr[n] = f;
        part[wid] = f * dd;                  // self-loop term f[n]*dis[n]
    }
    __syncthreads();
    if (threadIdx.x == 0) {
        float t = 0.f;
        #pragma unroll
        for (int w = 0; w < 8; ++w) t += part[w];
        atomicAdd(&score_scr[gidx], t);
    }
}

// -------- edge score: sum_d dis[d] * sum_{s in bucket[d]} f[s] --------
__global__ void __launch_bounds__(256) edge_score_kernel() {
    int wid  = threadIdx.x >> 5;
    int lane = threadIdx.x & 31;
    int n = blockIdx.x * 8 + wid;
    int gidx = blockIdx.x / (NNODE / 8);

    int cnt = cnt_scr[n];
    if (cnt > CAP) cnt = CAP;
    int start = n * CAP;

    float acc = 0.f;
    for (int base = lane; base < cnt; base += 32) {
        int s = bucket_scr[start + base];
        acc += f_scr[s];
    }
    #pragma unroll
    for (int off = 16; off; off >>= 1)
        acc += __shfl_down_sync(0xffffffffu, acc, off);

    __shared__ float part[8];
    if (lane == 0) part[wid] = acc * dis_scr[n];
    __syncthreads();
    if (threadIdx.x == 0) {
        float t = 0.f;
        #pragma unroll
        for (int w = 0; w < 8; ++w) t += part[w];
        atomicAdd(&score_scr[gidx], t);
    }
}

// -------- softmax over 5 graph scores --------
__global__ void softmax_kernel(const float* __restrict__ b2, float* __restrict__ out) {
    if (threadIdx.x == 0) {
        float s[NG], m = -1e30f;
        for (int g = 0; g < NG; ++g) {
            s[g] = score_scr[g] * (1.0f / (float)NNODE) + b2[0];
            m = fmaxf(m, s[g]);
        }
        float sum = 0.f, e[NG];
        for (int g = 0; g < NG; ++g) { e[g] = expf(s[g] - m); sum += e[g]; }
        for (int g = 0; g < NG; ++g) out[g] = e[g] / sum;
    }
}

extern "C" void kernel_launch(void* const* d_in, const int* in_sizes, int n_in,
                              void* d_out, int out_size) {
    const float* emb = (const float*)d_in[0];
    const void*  ei  = d_in[1];
    const float* W1  = (const float*)d_in[2];
    const float* b1  = (const float*)d_in[3];
    const float* W2  = (const float*)d_in[4];
    const float* b2  = (const float*)d_in[5];
    float* out = (float*)d_out;

    // one-time host-side resources (no device allocations)
    static cudaStream_t side = nullptr;
    static cudaEvent_t evFork = nullptr, evJoin = nullptr;
    static void *cntAddr = nullptr, *scoreAddr = nullptr;
    if (!side) {
        cudaStreamCreateWithFlags(&side, cudaStreamNonBlocking);
        cudaEventCreateWithFlags(&evFork, cudaEventDisableTiming);
        cudaEventCreateWithFlags(&evJoin, cudaEventDisableTiming);
        cudaGetSymbolAddress(&cntAddr, cnt_scr);
        cudaGetSymbolAddress(&scoreAddr, score_scr);
        cudaFuncSetAttribute((const void*)gemm_kernel,
                             cudaFuncAttributeMaxDynamicSharedMemorySize, GEMM_SMEM);
    }

    cudaMemsetAsync(cntAddr, 0, TOT * sizeof(int), 0);
    cudaMemsetAsync(scoreAddr, 0, NG * sizeof(float), 0);

    cudaEventRecord(evFork, 0);
    cudaStreamWaitEvent(side, evFork, 0);

    dim3 eg((NEDGE / 4 + 255) / 256, NG);
    fill_kernel<<<eg, 256>>>(ei);                                       // k1 (main)
    gemm_kernel<<<(TOT + 511) / 512, 256, GEMM_SMEM, side>>>(emb, W1);  // k2 (side)
    cudaEventRecord(evJoin, side);
    cudaStreamWaitEvent(0, evJoin, 0);

    disscale_kernel<<<(TOT + 255) / 256, 256>>>();                      // k3
    gather_kernel<<<TOT / 8, 256>>>(b1, W2);                            // k4 <- profile target
    edge_score_kernel<<<TOT / 8, 256>>>();                              // k5
    softmax_kernel<<<1, 32>>>(b2, out);                                 // k6
}

// round 6
// speedup vs baseline: 1.2565x; 1.2565x over previous
#include <cuda_runtime.h>
#include <cuda_bf16.h>

#define NNODE   100000
#define NEDGE   3200000
#define DIM     300
#define HID     16
#define NG      5
#define TOT     (NG*NNODE)      // 500000
#define TOTEDGE (NG*NEDGE)      // 16000000
#define CAP     80              // bucket slots per node; P(deg>=80)~5e-13 per node

// -------- scratch (no allocations allowed; __device__ globals) --------
__device__ __align__(16) float          g_scr[TOT*HID];   // raw emb@W1 (fp32)
__device__ __align__(16) unsigned short gb_scr[TOT*HID];  // scaled bf16 g (16MB)
__device__ int   bucket_scr[TOT*CAP];                     // 160MB: src lists by dst
__device__ int   cnt_scr[TOT];                            // in-degree
__device__ float dis_scr[TOT];
__device__ float f_scr[TOT];                              // f[n] = z[n]*dis[n]
__device__ float score_scr[NG];

__device__ __forceinline__ unsigned bf2pack(float a, float b) {
    __nv_bfloat162 t = __float22bfloat162_rn(make_float2(a, b));
    return *(unsigned*)&t;
}

// -------- bucket fill: per-block dtype detect, one atomic per edge --------
__global__ void fill_kernel(const void* __restrict__ ei) {
    __shared__ int s64;
    if (threadIdx.x < 32) {
        const unsigned long long* p = (const unsigned long long*)ei;
        unsigned long long a = p[threadIdx.x];
        unsigned long long b = p[threadIdx.x + 32];
        int bad = ((a >> 32) | (b >> 32)) != 0ULL;   // int32 data -> high words nonzero w.h.p.
        unsigned m = __ballot_sync(0xffffffffu, bad);
        if (threadIdx.x == 0) s64 = (m == 0);
    }
    __syncthreads();
    int is64 = s64;

    int e0 = (blockIdx.x * blockDim.x + threadIdx.x) * 4;
    if (e0 >= NEDGE) return;
    int gy = blockIdx.y;
    int nb = gy * NNODE;
    int s[4], d[4];
    if (is64) {
        const long long* base = (const long long*)ei + (long long)gy * 2 * NEDGE;
        longlong2 sa = *(const longlong2*)(base + e0);
        longlong2 sb = *(const longlong2*)(base + e0 + 2);
        longlong2 da = *(const longlong2*)(base + NEDGE + e0);
        longlong2 db = *(const longlong2*)(base + NEDGE + e0 + 2);
        s[0]=(int)sa.x; s[1]=(int)sa.y; s[2]=(int)sb.x; s[3]=(int)sb.y;
        d[0]=(int)da.x; d[1]=(int)da.y; d[2]=(int)db.x; d[3]=(int)db.y;
    } else {
        const int* base = (const int*)ei + (long long)gy * 2 * NEDGE;
        int4 sv = *(const int4*)(base + e0);
        int4 dv = *(const int4*)(base + NEDGE + e0);
        s[0]=sv.x; s[1]=sv.y; s[2]=sv.z; s[3]=sv.w;
        d[0]=dv.x; d[1]=dv.y; d[2]=dv.z; d[3]=dv.w;
    }
    #pragma unroll
    for (int r = 0; r < 4; ++r) {
        int ds = nb + d[r];
        int pos = atomicAdd(&cnt_scr[ds], 1);
        if (pos < CAP) bucket_scr[ds * CAP + pos] = nb + s[r];
    }
}

// -------- GEMM (raw): g[n][k] = sum_j emb[n][j]*W1[j][k]  (scalar FMA, reverted) --------
#define JC 30
#define SA_STRIDE 513
#define SW_FLOATS (DIM*HID)          // 4800
#define SA_FLOATS (JC*SA_STRIDE)     // 15390
#define GEMM_SMEM ((SW_FLOATS + SA_FLOATS) * 4)

#define STEP(ACC, A) \
    ACC[0]=fmaf(A,w0.x,ACC[0]);  ACC[1]=fmaf(A,w0.y,ACC[1]);  \
    ACC[2]=fmaf(A,w0.z,ACC[2]);  ACC[3]=fmaf(A,w0.w,ACC[3]);  \
    ACC[4]=fmaf(A,w1.x,ACC[4]);  ACC[5]=fmaf(A,w1.y,ACC[5]);  \
    ACC[6]=fmaf(A,w1.z,ACC[6]);  ACC[7]=fmaf(A,w1.w,ACC[7]);  \
    ACC[8]=fmaf(A,w2.x,ACC[8]);  ACC[9]=fmaf(A,w2.y,ACC[9]);  \
    ACC[10]=fmaf(A,w2.z,ACC[10]);ACC[11]=fmaf(A,w2.w,ACC[11]);\
    ACC[12]=fmaf(A,w3.x,ACC[12]);ACC[13]=fmaf(A,w3.y,ACC[13]);\
    ACC[14]=fmaf(A,w3.z,ACC[14]);ACC[15]=fmaf(A,w3.w,ACC[15]);

__global__ void __launch_bounds__(256) gemm_kernel(const float* __restrict__ emb,
                                                   const float* __restrict__ W1) {
    extern __shared__ float sm[];
    float* sW = sm;                // 4800 floats
    float* sA = sm + SW_FLOATS;    // [JC][513]
    int tid = threadIdx.x;
    int nbase = blockIdx.x * 512;

    for (int idx = tid; idx < SW_FLOATS; idx += 256) sW[idx] = W1[idx];

    float acc0[16], acc1[16];
    #pragma unroll
    for (int k = 0; k < 16; ++k) { acc0[k] = 0.f; acc1[k] = 0.f; }

    for (int c = 0; c < 10; ++c) {
        int j0 = c * JC;
        __syncthreads();
        #pragma unroll
        for (int it = 0; it < 30; ++it) {
            int idx = it * 256 + tid;
            int n = idx / 15;
            int jp = idx - n * 15;
            int gn = nbase + n;
            float2 v = make_float2(0.f, 0.f);
            if (gn < TOT)
                v = *(const float2*)(emb + (size_t)gn * DIM + j0 + 2 * jp);
            sA[(2 * jp)     * SA_STRIDE + n] = v.x;
            sA[(2 * jp + 1) * SA_STRIDE + n] = v.y;
        }
        __syncthreads();
        #pragma unroll
        for (int jl = 0; jl < JC; ++jl) {
            float a0 = sA[jl * SA_STRIDE + tid];
            float a1 = sA[jl * SA_STRIDE + 256 + tid];
            const float4* wr = (const float4*)(sW + (j0 + jl) * HID);
            float4 w0 = wr[0], w1 = wr[1], w2 = wr[2], w3 = wr[3];
            STEP(acc0, a0)
            STEP(acc1, a1)
        }
    }

    int gn0 = nbase + tid;
    int gn1 = nbase + 256 + tid;
    if (gn0 < TOT) {
        float4* o = (float4*)(g_scr + (size_t)gn0 * HID);
        o[0] = make_float4(acc0[0],  acc0[1],  acc0[2],  acc0[3]);
        o[1] = make_float4(acc0[4],  acc0[5],  acc0[6],  acc0[7]);
        o[2] = make_float4(acc0[8],  acc0[9],  acc0[10], acc0[11]);
        o[3] = make_float4(acc0[12], acc0[13], acc0[14], acc0[15]);
    }
    if (gn1 < TOT) {
        float4* o = (float4*)(g_scr + (size_t)gn1 * HID);
        o[0] = make_float4(acc1[0],  acc1[1],  acc1[2],  acc1[3]);
        o[1] = make_float4(acc1[4],  acc1[5],  acc1[6],  acc1[7]);
        o[2] = make_float4(acc1[8],  acc1[9],  acc1[10], acc1[11]);
        o[3] = make_float4(acc1[12], acc1[13], acc1[14], acc1[15]);
    }
}

// -------- fused: dis = rsqrt(deg+1); gb = bf16(g * dis) (thread per node) --------
__global__ void disscale_kernel() {
    int n = blockIdx.x * blockDim.x + threadIdx.x;
    if (n >= TOT) return;
    float dd = rsqrtf((float)cnt_scr[n] + 1.0f);
    dis_scr[n] = dd;
    const float4* gi = (const float4*)(g_scr + (size_t)n * HID);
    float4 a = gi[0], b = gi[1], c = gi[2], d = gi[3];
    uint4 o0, o1;
    o0.x = bf2pack(a.x*dd, a.y*dd);  o0.y = bf2pack(a.z*dd, a.w*dd);
    o0.z = bf2pack(b.x*dd, b.y*dd);  o0.w = bf2pack(b.z*dd, b.w*dd);
    o1.x = bf2pack(c.x*dd, c.y*dd);  o1.y = bf2pack(c.z*dd, c.w*dd);
    o1.z = bf2pack(d.x*dd, d.y*dd);  o1.w = bf2pack(d.z*dd, d.w*dd);
    uint4* go = (uint4*)(gb_scr + (size_t)n * HID);
    go[0] = o0; go[1] = o1;
}

// -------- gather: warp/node; 2 lanes per edge row (LDG.128), HADD2 accumulation --------
__global__ void __launch_bounds__(256) gather_kernel(const float* __restrict__ b1,
                                                     const float* __restrict__ W2) {
    int wid  = threadIdx.x >> 5;
    int lane = threadIdx.x & 31;
    int n = blockIdx.x * 8 + wid;            // 100000 % 8 == 0: blocks never straddle graphs
    int gidx = blockIdx.x / (NNODE / 8);

    int cnt = cnt_scr[n];
    if (cnt > CAP) cnt = CAP;
    int start = n * CAP;
    int q2 = lane & 1;                       // row half (16B = 8 dims)
    int es = lane >> 1;                      // edge slot 0..15

    const uint4* gbp = (const uint4*)gb_scr; // row = 2 × uint4

    __nv_bfloat162 acc0, acc1, acc2, acc3;
    {
        __nv_bfloat162 z = __float2bfloat162_rn(0.f);
        acc0 = z; acc1 = z; acc2 = z; acc3 = z;
    }

    for (int base = 0; base < cnt; base += 32) {
        int rem = cnt - base;
        int m = rem < 32 ? rem : 32;
        int sv = (lane < m) ? bucket_scr[start + base + lane] : 0;
        if (m == 32) {
            #pragma unroll
            for (int j = 0; j < 2; ++j) {
                int s = __shfl_sync(0xffffffffu, sv, j * 16 + es);
                uint4 v = gbp[s * 2 + q2];
                acc0 = __hadd2(acc0, *(__nv_bfloat162*)&v.x);
                acc1 = __hadd2(acc1, *(__nv_bfloat162*)&v.y);
                acc2 = __hadd2(acc2, *(__nv_bfloat162*)&v.z);
                acc3 = __hadd2(acc3, *(__nv_bfloat162*)&v.w);
            }
        } else {
            #pragma unroll
            for (int j = 0; j < 2; ++j) {
                int e = j * 16 + es;
                int s = __shfl_sync(0xffffffffu, sv, e);
                if (e < m) {
                    uint4 v = gbp[s * 2 + q2];
                    acc0 = __hadd2(acc0, *(__nv_bfloat162*)&v.x);
                    acc1 = __hadd2(acc1, *(__nv_bfloat162*)&v.y);
                    acc2 = __hadd2(acc2, *(__nv_bfloat162*)&v.z);
                    acc3 = __hadd2(acc3, *(__nv_bfloat162*)&v.w);
                }
            }
        }
    }

    // convert to fp32 (8 dims per lane) and reduce across the 16 edge slots
    float fa[8];
    { float2 t;
      t = __bfloat1622float2(acc0); fa[0]=t.x; fa[1]=t.y;
      t = __bfloat1622float2(acc1); fa[2]=t.x; fa[3]=t.y;
      t = __bfloat1622float2(acc2); fa[4]=t.x; fa[5]=t.y;
      t = __bfloat1622float2(acc3); fa[6]=t.x; fa[7]=t.y; }
    #pragma unroll
    for (int off = 16; off >= 2; off >>= 1) {
        #pragma unroll
        for (int i = 0; i < 8; ++i)
            fa[i] += __shfl_down_sync(0xffffffffu, fa[i], off);
    }

    // lanes 0,1 hold dims [0..7] / [8..15]
    float dd = dis_scr[n];
    float zp = 0.f;
    if (lane < 2) {
        uint4 gv = gbp[n * 2 + q2];
        float2 g0 = __bfloat1622float2(*(__nv_bfloat162*)&gv.x);
        float2 g1 = __bfloat1622float2(*(__nv_bfloat162*)&gv.y);
        float2 g2 = __bfloat1622float2(*(__nv_bfloat162*)&gv.z);
        float2 g3 = __bfloat1622float2(*(__nv_bfloat162*)&gv.w);
        float gg[8] = {g0.x,g0.y,g1.x,g1.y,g2.x,g2.y,g3.x,g3.y};
        float4 bbA = __ldg((const float4*)b1 + q2 * 2);
        float4 bbB = __ldg((const float4*)b1 + q2 * 2 + 1);
        float4 wwA = __ldg((const float4*)W2 + q2 * 2);
        float4 wwB = __ldg((const float4*)W2 + q2 * 2 + 1);
        float bb[8] = {bbA.x,bbA.y,bbA.z,bbA.w,bbB.x,bbB.y,bbB.z,bbB.w};
        float ww[8] = {wwA.x,wwA.y,wwA.z,wwA.w,wwB.x,wwB.y,wwB.z,wwB.w};
        #pragma unroll
        for (int i = 0; i < 8; ++i) {
            float h = fmaxf(fmaf(dd, fa[i] + gg[i], bb[i]), 0.f);
            zp = fmaf(h, ww[i], zp);
        }
    }
    zp += __shfl_xor_sync(0xffffffffu, zp, 1);   // lane0 = full dot

    __shared__ float part[8];
    if (lane == 0) {
        float f = zp * dd;                   // f[n] = z[n]*dis[n]
        f_scr[n] = f;
        part[wid] = f * dd;                  // self-loop term f[n]*dis[n]
    }
    __syncthreads();
    if (threadIdx.x == 0) {
        float t = 0.f;
        #pragma unroll
        for (int w = 0; w < 8; ++w) t += part[w];
        atomicAdd(&score_scr[gidx], t);
    }
}

// -------- edge score: sum_d dis[d] * sum_{s in bucket[d]} f[s] --------
__global__ void __launch_bounds__(256) edge_score_kernel() {
    int wid  = threadIdx.x >> 5;
    int lane = threadIdx.x & 31;
    int n = blockIdx.x * 8 + wid;
    int gidx = blockIdx.x / (NNODE / 8);

    int cnt = cnt_scr[n];
    if (cnt > CAP) cnt = CAP;
    int start = n * CAP;

    float acc = 0.f;
    for (int base = lane; base < cnt; base += 32) {
        int s = bucket_scr[start + base];
        acc += f_scr[s];
    }
    #pragma unroll
    for (int off = 16; off; off >>= 1)
        acc += __shfl_down_sync(0xffffffffu, acc, off);

    __shared__ float part[8];
    if (lane == 0) part[wid] = acc * dis_scr[n];
    __syncthreads();
    if (threadIdx.x == 0) {
        float t = 0.f;
        #pragma unroll
        for (int w = 0; w < 8; ++w) t += part[w];
        atomicAdd(&score_scr[gidx], t);
    }
}

// -------- softmax over 5 graph scores --------
__global__ void softmax_kernel(const float* __restrict__ b2, float* __restrict__ out) {
    if (threadIdx.x == 0) {
        float s[NG], m = -1e30f;
        for (int g = 0; g < NG; ++g) {
            s[g] = score_scr[g] * (1.0f / (float)NNODE) + b2[0];
            m = fmaxf(m, s[g]);
        }
        float sum = 0.f, e[NG];
        for (int g = 0; g < NG; ++g) { e[g] = expf(s[g] - m); sum += e[g]; }
        for (int g = 0; g < NG; ++g) out[g] = e[g] / sum;
    }
}

extern "C" void kernel_launch(void* const* d_in, const int* in_sizes, int n_in,
                              void* d_out, int out_size) {
    const float* emb = (const float*)d_in[0];
    const void*  ei  = d_in[1];
    const float* W1  = (const float*)d_in[2];
    const float* b1  = (const float*)d_in[3];
    const float* W2  = (const float*)d_in[4];
    const float* b2  = (const float*)d_in[5];
    float* out = (float*)d_out;

    // one-time host-side resources (no device allocations)
    static cudaStream_t side = nullptr;
    static cudaEvent_t evFork = nullptr, evJoin = nullptr;
    static void *cntAddr = nullptr, *scoreAddr = nullptr;
    if (!side) {
        cudaStreamCreateWithFlags(&side, cudaStreamNonBlocking);
        cudaEventCreateWithFlags(&evFork, cudaEventDisableTiming);
        cudaEventCreateWithFlags(&evJoin, cudaEventDisableTiming);
        cudaGetSymbolAddress(&cntAddr, cnt_scr);
        cudaGetSymbolAddress(&scoreAddr, score_scr);
        cudaFuncSetAttribute((const void*)gemm_kernel,
                             cudaFuncAttributeMaxDynamicSharedMemorySize, GEMM_SMEM);
    }

    cudaMemsetAsync(cntAddr, 0, TOT * sizeof(int), 0);
    cudaMemsetAsync(scoreAddr, 0, NG * sizeof(float), 0);

    cudaEventRecord(evFork, 0);
    cudaStreamWaitEvent(side, evFork, 0);

    dim3 eg((NEDGE / 4 + 255) / 256, NG);
    fill_kernel<<<eg, 256>>>(ei);                                       // main stream
    gemm_kernel<<<(TOT + 511) / 512, 256, GEMM_SMEM, side>>>(emb, W1);  // side stream
    cudaEventRecord(evJoin, side);
    cudaStreamWaitEvent(0, evJoin, 0);

    disscale_kernel<<<(TOT + 255) / 256, 256>>>();
    gather_kernel<<<TOT / 8, 256>>>(b1, W2);
    edge_score_kernel<<<TOT / 8, 256>>>();
    softmax_kernel<<<1, 32>>>(b2, out);
}

// round 7
// speedup vs baseline: 1.2939x; 1.0298x over previous
#include <cuda_runtime.h>
#include <cuda_bf16.h>

#define NNODE   100000
#define NEDGE   3200000
#define DIM     300
#define HID     16
#define NG      5
#define TOT     (NG*NNODE)      // 500000
#define TOTEDGE (NG*NEDGE)      // 16000000
#define CAP     80              // bucket slots per node; P(deg>=80)~5e-13 per node

// -------- scratch (no allocations allowed; __device__ globals) --------
__device__ __align__(16) float          g_scr[TOT*HID];   // raw emb@W1 (fp32)
__device__ __align__(16) unsigned short gb_scr[TOT*HID];  // scaled bf16 g (16MB)
__device__ int   bucket_scr[TOT*CAP];                     // 160MB: src lists by dst
__device__ int   cnt_scr[TOT];                            // in-degree
__device__ float dis_scr[TOT];
__device__ float f_scr[TOT];                              // f[n] = z[n]*dis[n]
__device__ float score_scr[NG];

__device__ __forceinline__ unsigned bf2pack(float a, float b) {
    __nv_bfloat162 t = __float22bfloat162_rn(make_float2(a, b));
    return *(unsigned*)&t;
}
__device__ __forceinline__ __nv_bfloat162 shfl_down_bf2(__nv_bfloat162 v, int off) {
    unsigned u = __shfl_down_sync(0xffffffffu, *(unsigned*)&v, off);
    return *(__nv_bfloat162*)&u;
}

// -------- bucket fill: per-block dtype detect, one atomic per edge --------
__global__ void fill_kernel(const void* __restrict__ ei) {
    __shared__ int s64;
    if (threadIdx.x < 32) {
        const unsigned long long* p = (const unsigned long long*)ei;
        unsigned long long a = p[threadIdx.x];
        unsigned long long b = p[threadIdx.x + 32];
        int bad = ((a >> 32) | (b >> 32)) != 0ULL;   // int32 data -> high words nonzero w.h.p.
        unsigned m = __ballot_sync(0xffffffffu, bad);
        if (threadIdx.x == 0) s64 = (m == 0);
    }
    __syncthreads();
    int is64 = s64;

    int e0 = (blockIdx.x * blockDim.x + threadIdx.x) * 4;
    if (e0 >= NEDGE) return;
    int gy = blockIdx.y;
    int nb = gy * NNODE;
    int s[4], d[4];
    if (is64) {
        const long long* base = (const long long*)ei + (long long)gy * 2 * NEDGE;
        longlong2 sa = *(const longlong2*)(base + e0);
        longlong2 sb = *(const longlong2*)(base + e0 + 2);
        longlong2 da = *(const longlong2*)(base + NEDGE + e0);
        longlong2 db = *(const longlong2*)(base + NEDGE + e0 + 2);
        s[0]=(int)sa.x; s[1]=(int)sa.y; s[2]=(int)sb.x; s[3]=(int)sb.y;
        d[0]=(int)da.x; d[1]=(int)da.y; d[2]=(int)db.x; d[3]=(int)db.y;
    } else {
        const int* base = (const int*)ei + (long long)gy * 2 * NEDGE;
        int4 sv = *(const int4*)(base + e0);
        int4 dv = *(const int4*)(base + NEDGE + e0);
        s[0]=sv.x; s[1]=sv.y; s[2]=sv.z; s[3]=sv.w;
        d[0]=dv.x; d[1]=dv.y; d[2]=dv.z; d[3]=dv.w;
    }
    #pragma unroll
    for (int r = 0; r < 4; ++r) {
        int ds = nb + d[r];
        int pos = atomicAdd(&cnt_scr[ds], 1);
        if (pos < CAP) bucket_scr[ds * CAP + pos] = nb + s[r];
    }
}

// -------- GEMM (raw): g[n][k] = sum_j emb[n][j]*W1[j][k]  (scalar FMA) --------
#define JC 30
#define SA_STRIDE 513
#define SW_FLOATS (DIM*HID)          // 4800
#define SA_FLOATS (JC*SA_STRIDE)     // 15390
#define GEMM_SMEM ((SW_FLOATS + SA_FLOATS) * 4)

#define STEP(ACC, A) \
    ACC[0]=fmaf(A,w0.x,ACC[0]);  ACC[1]=fmaf(A,w0.y,ACC[1]);  \
    ACC[2]=fmaf(A,w0.z,ACC[2]);  ACC[3]=fmaf(A,w0.w,ACC[3]);  \
    ACC[4]=fmaf(A,w1.x,ACC[4]);  ACC[5]=fmaf(A,w1.y,ACC[5]);  \
    ACC[6]=fmaf(A,w1.z,ACC[6]);  ACC[7]=fmaf(A,w1.w,ACC[7]);  \
    ACC[8]=fmaf(A,w2.x,ACC[8]);  ACC[9]=fmaf(A,w2.y,ACC[9]);  \
    ACC[10]=fmaf(A,w2.z,ACC[10]);ACC[11]=fmaf(A,w2.w,ACC[11]);\
    ACC[12]=fmaf(A,w3.x,ACC[12]);ACC[13]=fmaf(A,w3.y,ACC[13]);\
    ACC[14]=fmaf(A,w3.z,ACC[14]);ACC[15]=fmaf(A,w3.w,ACC[15]);

__global__ void __launch_bounds__(256) gemm_kernel(const float* __restrict__ emb,
                                                   const float* __restrict__ W1) {
    extern __shared__ float sm[];
    float* sW = sm;                // 4800 floats
    float* sA = sm + SW_FLOATS;    // [JC][513]
    int tid = threadIdx.x;
    int nbase = blockIdx.x * 512;

    for (int idx = tid; idx < SW_FLOATS; idx += 256) sW[idx] = W1[idx];

    float acc0[16], acc1[16];
    #pragma unroll
    for (int k = 0; k < 16; ++k) { acc0[k] = 0.f; acc1[k] = 0.f; }

    for (int c = 0; c < 10; ++c) {
        int j0 = c * JC;
        __syncthreads();
        #pragma unroll
        for (int it = 0; it < 30; ++it) {
            int idx = it * 256 + tid;
            int n = idx / 15;
            int jp = idx - n * 15;
            int gn = nbase + n;
            float2 v = make_float2(0.f, 0.f);
            if (gn < TOT)
                v = *(const float2*)(emb + (size_t)gn * DIM + j0 + 2 * jp);
            sA[(2 * jp)     * SA_STRIDE + n] = v.x;
            sA[(2 * jp + 1) * SA_STRIDE + n] = v.y;
        }
        __syncthreads();
        #pragma unroll
        for (int jl = 0; jl < JC; ++jl) {
            float a0 = sA[jl * SA_STRIDE + tid];
            float a1 = sA[jl * SA_STRIDE + 256 + tid];
            const float4* wr = (const float4*)(sW + (j0 + jl) * HID);
            float4 w0 = wr[0], w1 = wr[1], w2 = wr[2], w3 = wr[3];
            STEP(acc0, a0)
            STEP(acc1, a1)
        }
    }

    int gn0 = nbase + tid;
    int gn1 = nbase + 256 + tid;
    if (gn0 < TOT) {
        float4* o = (float4*)(g_scr + (size_t)gn0 * HID);
        o[0] = make_float4(acc0[0],  acc0[1],  acc0[2],  acc0[3]);
        o[1] = make_float4(acc0[4],  acc0[5],  acc0[6],  acc0[7]);
        o[2] = make_float4(acc0[8],  acc0[9],  acc0[10], acc0[11]);
        o[3] = make_float4(acc0[12], acc0[13], acc0[14], acc0[15]);
    }
    if (gn1 < TOT) {
        float4* o = (float4*)(g_scr + (size_t)gn1 * HID);
        o[0] = make_float4(acc1[0],  acc1[1],  acc1[2],  acc1[3]);
        o[1] = make_float4(acc1[4],  acc1[5],  acc1[6],  acc1[7]);
        o[2] = make_float4(acc1[8],  acc1[9],  acc1[10], acc1[11]);
        o[3] = make_float4(acc1[12], acc1[13], acc1[14], acc1[15]);
    }
}

// -------- fused: dis = rsqrt(deg+1); gb = bf16(g * dis) (thread per node) --------
__global__ void disscale_kernel() {
    int n = blockIdx.x * blockDim.x + threadIdx.x;
    if (n >= TOT) return;
    float dd = rsqrtf((float)cnt_scr[n] + 1.0f);
    dis_scr[n] = dd;
    const float4* gi = (const float4*)(g_scr + (size_t)n * HID);
    float4 a = gi[0], b = gi[1], c = gi[2], d = gi[3];
    uint4 o0, o1;
    o0.x = bf2pack(a.x*dd, a.y*dd);  o0.y = bf2pack(a.z*dd, a.w*dd);
    o0.z = bf2pack(b.x*dd, b.y*dd);  o0.w = bf2pack(b.z*dd, b.w*dd);
    o1.x = bf2pack(c.x*dd, c.y*dd);  o1.y = bf2pack(c.z*dd, c.w*dd);
    o1.z = bf2pack(d.x*dd, d.y*dd);  o1.w = bf2pack(d.z*dd, d.w*dd);
    uint4* go = (uint4*)(gb_scr + (size_t)n * HID);
    go[0] = o0; go[1] = o1;
}

// -------- gather: warp/node; paired lanes read bucket directly (L1 broadcast), --------
// -------- no shuffles in main loop; packed bf16x2 slot reduction.             --------
__global__ void __launch_bounds__(256) gather_kernel(const float* __restrict__ b1,
                                                     const float* __restrict__ W2) {
    int wid  = threadIdx.x >> 5;
    int lane = threadIdx.x & 31;
    int n = blockIdx.x * 8 + wid;            // 100000 % 8 == 0: blocks never straddle graphs
    int gidx = blockIdx.x / (NNODE / 8);

    int cnt = cnt_scr[n];
    if (cnt > CAP) cnt = CAP;
    int start = n * CAP;
    int q2 = lane & 1;                       // row half (16B = 8 dims)
    int es = lane >> 1;                      // edge slot 0..15

    const uint4* gbp = (const uint4*)gb_scr; // row = 2 × uint4

    __nv_bfloat162 acc0, acc1, acc2, acc3;
    {
        __nv_bfloat162 z = __float2bfloat162_rn(0.f);
        acc0 = z; acc1 = z; acc2 = z; acc3 = z;
    }

    // paired lanes (2i, 2i+1) load the same bucket word -> L1 broadcast, no shfl
    for (int i = es; i < cnt; i += 16) {
        int s = bucket_scr[start + i];
        uint4 v = gbp[s * 2 + q2];
        acc0 = __hadd2(acc0, *(__nv_bfloat162*)&v.x);
        acc1 = __hadd2(acc1, *(__nv_bfloat162*)&v.y);
        acc2 = __hadd2(acc2, *(__nv_bfloat162*)&v.z);
        acc3 = __hadd2(acc3, *(__nv_bfloat162*)&v.w);
    }

    // packed reduction across 16 edge slots (same q2 partition): 4 levels
    #pragma unroll
    for (int off = 16; off >= 2; off >>= 1) {
        acc0 = __hadd2(acc0, shfl_down_bf2(acc0, off));
        acc1 = __hadd2(acc1, shfl_down_bf2(acc1, off));
        acc2 = __hadd2(acc2, shfl_down_bf2(acc2, off));
        acc3 = __hadd2(acc3, shfl_down_bf2(acc3, off));
    }

    // lanes 0,1 hold dims [0..7] / [8..15]
    float dd = dis_scr[n];
    float zp = 0.f;
    if (lane < 2) {
        float fa[8];
        { float2 t;
          t = __bfloat1622float2(acc0); fa[0]=t.x; fa[1]=t.y;
          t = __bfloat1622float2(acc1); fa[2]=t.x; fa[3]=t.y;
          t = __bfloat1622float2(acc2); fa[4]=t.x; fa[5]=t.y;
          t = __bfloat1622float2(acc3); fa[6]=t.x; fa[7]=t.y; }
        uint4 gv = gbp[n * 2 + q2];
        float2 g0 = __bfloat1622float2(*(__nv_bfloat162*)&gv.x);
        float2 g1 = __bfloat1622float2(*(__nv_bfloat162*)&gv.y);
        float2 g2 = __bfloat1622float2(*(__nv_bfloat162*)&gv.z);
        float2 g3 = __bfloat1622float2(*(__nv_bfloat162*)&gv.w);
        float gg[8] = {g0.x,g0.y,g1.x,g1.y,g2.x,g2.y,g3.x,g3.y};
        float4 bbA = __ldg((const float4*)b1 + q2 * 2);
        float4 bbB = __ldg((const float4*)b1 + q2 * 2 + 1);
        float4 wwA = __ldg((const float4*)W2 + q2 * 2);
        float4 wwB = __ldg((const float4*)W2 + q2 * 2 + 1);
        float bb[8] = {bbA.x,bbA.y,bbA.z,bbA.w,bbB.x,bbB.y,bbB.z,bbB.w};
        float ww[8] = {wwA.x,wwA.y,wwA.z,wwA.w,wwB.x,wwB.y,wwB.z,wwB.w};
        #pragma unroll
        for (int i = 0; i < 8; ++i) {
            float h = fmaxf(fmaf(dd, fa[i] + gg[i], bb[i]), 0.f);
            zp = fmaf(h, ww[i], zp);
        }
    }
    zp += __shfl_xor_sync(0xffffffffu, zp, 1);   // lane0 = full dot

    __shared__ float part[8];
    if (lane == 0) {
        float f = zp * dd;                   // f[n] = z[n]*dis[n]
        f_scr[n] = f;
        part[wid] = f * dd;                  // self-loop term f[n]*dis[n]
    }
    __syncthreads();
    if (threadIdx.x == 0) {
        float t = 0.f;
        #pragma unroll
        for (int w = 0; w < 8; ++w) t += part[w];
        atomicAdd(&score_scr[gidx], t);
    }
}

// -------- edge score: sum_d dis[d] * sum_{s in bucket[d]} f[s] --------
__global__ void __launch_bounds__(256) edge_score_kernel() {
    int wid  = threadIdx.x >> 5;
    int lane = threadIdx.x & 31;
    int n = blockIdx.x * 8 + wid;
    int gidx = blockIdx.x / (NNODE / 8);

    int cnt = cnt_scr[n];
    if (cnt > CAP) cnt = CAP;
    int start = n * CAP;

    float acc = 0.f;
    for (int base = lane; base < cnt; base += 32) {
        int s = bucket_scr[start + base];
        acc += f_scr[s];
    }
    #pragma unroll
    for (int off = 16; off; off >>= 1)
        acc += __shfl_down_sync(0xffffffffu, acc, off);

    __shared__ float part[8];
    if (lane == 0) part[wid] = acc * dis_scr[n];
    __syncthreads();
    if (threadIdx.x == 0) {
        float t = 0.f;
        #pragma unroll
        for (int w = 0; w < 8; ++w) t += part[w];
        atomicAdd(&score_scr[gidx], t);
    }
}

// -------- softmax over 5 graph scores --------
__global__ void softmax_kernel(const float* __restrict__ b2, float* __restrict__ out) {
    if (threadIdx.x == 0) {
        float s[NG], m = -1e30f;
        for (int g = 0; g < NG; ++g) {
            s[g] = score_scr[g] * (1.0f / (float)NNODE) + b2[0];
            m = fmaxf(m, s[g]);
        }
        float sum = 0.f, e[NG];
        for (int g = 0; g < NG; ++g) { e[g] = expf(s[g] - m); sum += e[g]; }
        for (int g = 0; g < NG; ++g) out[g] = e[g] / sum;
    }
}

extern "C" void kernel_launch(void* const* d_in, const int* in_sizes, int n_in,
                              void* d_out, int out_size) {
    const float* emb = (const float*)d_in[0];
    const void*  ei  = d_in[1];
    const float* W1  = (const float*)d_in[2];
    const float* b1  = (const float*)d_in[3];
    const float* W2  = (const float*)d_in[4];
    const float* b2  = (const float*)d_in[5];
    float* out = (float*)d_out;

    // one-time host-side resources (no device allocations)
    static cudaStream_t side = nullptr;
    static cudaEvent_t evFork = nullptr, evJoin = nullptr;
    static void *cntAddr = nullptr, *scoreAddr = nullptr;
    if (!side) {
        cudaStreamCreateWithFlags(&side, cudaStreamNonBlocking);
        cudaEventCreateWithFlags(&evFork, cudaEventDisableTiming);
        cudaEventCreateWithFlags(&evJoin, cudaEventDisableTiming);
        cudaGetSymbolAddress(&cntAddr, cnt_scr);
        cudaGetSymbolAddress(&scoreAddr, score_scr);
        cudaFuncSetAttribute((const void*)gemm_kernel,
                             cudaFuncAttributeMaxDynamicSharedMemorySize, GEMM_SMEM);
    }

    cudaMemsetAsync(cntAddr, 0, TOT * sizeof(int), 0);
    cudaMemsetAsync(scoreAddr, 0, NG * sizeof(float), 0);

    cudaEventRecord(evFork, 0);
    cudaStreamWaitEvent(side, evFork, 0);

    dim3 eg((NEDGE / 4 + 255) / 256, NG);
    fill_kernel<<<eg, 256>>>(ei);                                       // main stream
    gemm_kernel<<<(TOT + 511) / 512, 256, GEMM_SMEM, side>>>(emb, W1);  // side stream
    cudaEventRecord(evJoin, side);
    cudaStreamWaitEvent(0, evJoin, 0);

    disscale_kernel<<<(TOT + 255) / 256, 256>>>();
    gather_kernel<<<TOT / 8, 256>>>(b1, W2);
    edge_score_kernel<<<TOT / 8, 256>>>();
    softmax_kernel<<<1, 32>>>(b2, out);
}

// round 8
// speedup vs baseline: 1.3127x; 1.0146x over previous
#include <cuda_runtime.h>
#include <cuda_bf16.h>

#define NNODE   100000
#define NEDGE   3200000
#define DIM     300
#define HID     16
#define NG      5
#define TOT     (NG*NNODE)      // 500000
#define TOTEDGE (NG*NEDGE)      // 16000000
#define CAP     80              // bucket slots per node; P(deg>=80)~5e-13 per node

// -------- scratch (no allocations allowed; __device__ globals) --------
__device__ __align__(16) float          g_scr[TOT*HID];   // raw emb@W1 (fp32)
__device__ __align__(16) unsigned short gb_scr[TOT*HID];  // scaled bf16 g (16MB)
__device__ int   bucket_scr[TOT*CAP];                     // 160MB: src lists by dst
__device__ int   cnt_scr[TOT];                            // in-degree
__device__ float dis_scr[TOT];
__device__ float f_scr[TOT];                              // f[n] = z[n]*dis[n]
__device__ float c_scr[TOT];                              // c[s] = sum_out dis[dst]
__device__ float score_scr[NG];

__device__ __forceinline__ unsigned bf2pack(float a, float b) {
    __nv_bfloat162 t = __float22bfloat162_rn(make_float2(a, b));
    return *(unsigned*)&t;
}
__device__ __forceinline__ __nv_bfloat162 shfl_down_bf2(__nv_bfloat162 v, int off) {
    unsigned u = __shfl_down_sync(0xffffffffu, *(unsigned*)&v, off);
    return *(__nv_bfloat162*)&u;
}

// -------- bucket fill: per-block dtype detect, one atomic per edge --------
__global__ void fill_kernel(const void* __restrict__ ei) {
    __shared__ int s64;
    if (threadIdx.x < 32) {
        const unsigned long long* p = (const unsigned long long*)ei;
        unsigned long long a = p[threadIdx.x];
        unsigned long long b = p[threadIdx.x + 32];
        int bad = ((a >> 32) | (b >> 32)) != 0ULL;   // int32 data -> high words nonzero w.h.p.
        unsigned m = __ballot_sync(0xffffffffu, bad);
        if (threadIdx.x == 0) s64 = (m == 0);
    }
    __syncthreads();
    int is64 = s64;

    int e0 = (blockIdx.x * blockDim.x + threadIdx.x) * 4;
    if (e0 >= NEDGE) return;
    int gy = blockIdx.y;
    int nb = gy * NNODE;
    int s[4], d[4];
    if (is64) {
        const long long* base = (const long long*)ei + (long long)gy * 2 * NEDGE;
        longlong2 sa = *(const longlong2*)(base + e0);
        longlong2 sb = *(const longlong2*)(base + e0 + 2);
        longlong2 da = *(const longlong2*)(base + NEDGE + e0);
        longlong2 db = *(const longlong2*)(base + NEDGE + e0 + 2);
        s[0]=(int)sa.x; s[1]=(int)sa.y; s[2]=(int)sb.x; s[3]=(int)sb.y;
        d[0]=(int)da.x; d[1]=(int)da.y; d[2]=(int)db.x; d[3]=(int)db.y;
    } else {
        const int* base = (const int*)ei + (long long)gy * 2 * NEDGE;
        int4 sv = *(const int4*)(base + e0);
        int4 dv = *(const int4*)(base + NEDGE + e0);
        s[0]=sv.x; s[1]=sv.y; s[2]=sv.z; s[3]=sv.w;
        d[0]=dv.x; d[1]=dv.y; d[2]=dv.z; d[3]=dv.w;
    }
    #pragma unroll
    for (int r = 0; r < 4; ++r) {
        int ds = nb + d[r];
        int pos = atomicAdd(&cnt_scr[ds], 1);
        if (pos < CAP) bucket_scr[ds * CAP + pos] = nb + s[r];
    }
}

// -------- GEMM (raw): g[n][k] = sum_j emb[n][j]*W1[j][k]  (scalar FMA) --------
#define JC 30
#define SA_STRIDE 513
#define SW_FLOATS (DIM*HID)          // 4800
#define SA_FLOATS (JC*SA_STRIDE)     // 15390
#define GEMM_SMEM ((SW_FLOATS + SA_FLOATS) * 4)

#define STEP(ACC, A) \
    ACC[0]=fmaf(A,w0.x,ACC[0]);  ACC[1]=fmaf(A,w0.y,ACC[1]);  \
    ACC[2]=fmaf(A,w0.z,ACC[2]);  ACC[3]=fmaf(A,w0.w,ACC[3]);  \
    ACC[4]=fmaf(A,w1.x,ACC[4]);  ACC[5]=fmaf(A,w1.y,ACC[5]);  \
    ACC[6]=fmaf(A,w1.z,ACC[6]);  ACC[7]=fmaf(A,w1.w,ACC[7]);  \
    ACC[8]=fmaf(A,w2.x,ACC[8]);  ACC[9]=fmaf(A,w2.y,ACC[9]);  \
    ACC[10]=fmaf(A,w2.z,ACC[10]);ACC[11]=fmaf(A,w2.w,ACC[11]);\
    ACC[12]=fmaf(A,w3.x,ACC[12]);ACC[13]=fmaf(A,w3.y,ACC[13]);\
    ACC[14]=fmaf(A,w3.z,ACC[14]);ACC[15]=fmaf(A,w3.w,ACC[15]);

__global__ void __launch_bounds__(256) gemm_kernel(const float* __restrict__ emb,
                                                   const float* __restrict__ W1) {
    extern __shared__ float sm[];
    float* sW = sm;                // 4800 floats
    float* sA = sm + SW_FLOATS;    // [JC][513]
    int tid = threadIdx.x;
    int nbase = blockIdx.x * 512;

    for (int idx = tid; idx < SW_FLOATS; idx += 256) sW[idx] = W1[idx];

    float acc0[16], acc1[16];
    #pragma unroll
    for (int k = 0; k < 16; ++k) { acc0[k] = 0.f; acc1[k] = 0.f; }

    for (int c = 0; c < 10; ++c) {
        int j0 = c * JC;
        __syncthreads();
        #pragma unroll
        for (int it = 0; it < 30; ++it) {
            int idx = it * 256 + tid;
            int n = idx / 15;
            int jp = idx - n * 15;
            int gn = nbase + n;
            float2 v = make_float2(0.f, 0.f);
            if (gn < TOT)
                v = *(const float2*)(emb + (size_t)gn * DIM + j0 + 2 * jp);
            sA[(2 * jp)     * SA_STRIDE + n] = v.x;
            sA[(2 * jp + 1) * SA_STRIDE + n] = v.y;
        }
        __syncthreads();
        #pragma unroll
        for (int jl = 0; jl < JC; ++jl) {
            float a0 = sA[jl * SA_STRIDE + tid];
            float a1 = sA[jl * SA_STRIDE + 256 + tid];
            const float4* wr = (const float4*)(sW + (j0 + jl) * HID);
            float4 w0 = wr[0], w1 = wr[1], w2 = wr[2], w3 = wr[3];
            STEP(acc0, a0)
            STEP(acc1, a1)
        }
    }

    int gn0 = nbase + tid;
    int gn1 = nbase + 256 + tid;
    if (gn0 < TOT) {
        float4* o = (float4*)(g_scr + (size_t)gn0 * HID);
        o[0] = make_float4(acc0[0],  acc0[1],  acc0[2],  acc0[3]);
        o[1] = make_float4(acc0[4],  acc0[5],  acc0[6],  acc0[7]);
        o[2] = make_float4(acc0[8],  acc0[9],  acc0[10], acc0[11]);
        o[3] = make_float4(acc0[12], acc0[13], acc0[14], acc0[15]);
    }
    if (gn1 < TOT) {
        float4* o = (float4*)(g_scr + (size_t)gn1 * HID);
        o[0] = make_float4(acc1[0],  acc1[1],  acc1[2],  acc1[3]);
        o[1] = make_float4(acc1[4],  acc1[5],  acc1[6],  acc1[7]);
        o[2] = make_float4(acc1[8],  acc1[9],  acc1[10], acc1[11]);
        o[3] = make_float4(acc1[12], acc1[13], acc1[14], acc1[15]);
    }
}

// -------- dis = rsqrt(deg+1) (needs only cnt, runs right after fill) --------
__global__ void dis_kernel() {
    int n = blockIdx.x * blockDim.x + threadIdx.x;
    if (n < TOT) dis_scr[n] = rsqrtf((float)cnt_scr[n] + 1.0f);
}

// -------- c accumulation: c[src] += dis[dst] per edge (runs ∥ gather) --------
__global__ void c_kernel(const void* __restrict__ ei) {
    __shared__ int s64;
    if (threadIdx.x < 32) {
        const unsigned long long* p = (const unsigned long long*)ei;
        unsigned long long a = p[threadIdx.x];
        unsigned long long b = p[threadIdx.x + 32];
        int bad = ((a >> 32) | (b >> 32)) != 0ULL;
        unsigned m = __ballot_sync(0xffffffffu, bad);
        if (threadIdx.x == 0) s64 = (m == 0);
    }
    __syncthreads();
    int is64 = s64;

    int e0 = (blockIdx.x * blockDim.x + threadIdx.x) * 4;
    if (e0 >= NEDGE) return;
    int gy = blockIdx.y;
    int nb = gy * NNODE;
    int s[4], d[4];
    if (is64) {
        const long long* base = (const long long*)ei + (long long)gy * 2 * NEDGE;
        longlong2 sa = *(const longlong2*)(base + e0);
        longlong2 sb = *(const longlong2*)(base + e0 + 2);
        longlong2 da = *(const longlong2*)(base + NEDGE + e0);
        longlong2 db = *(const longlong2*)(base + NEDGE + e0 + 2);
        s[0]=(int)sa.x; s[1]=(int)sa.y; s[2]=(int)sb.x; s[3]=(int)sb.y;
        d[0]=(int)da.x; d[1]=(int)da.y; d[2]=(int)db.x; d[3]=(int)db.y;
    } else {
        const int* base = (const int*)ei + (long long)gy * 2 * NEDGE;
        int4 sv = *(const int4*)(base + e0);
        int4 dv = *(const int4*)(base + NEDGE + e0);
        s[0]=sv.x; s[1]=sv.y; s[2]=sv.z; s[3]=sv.w;
        d[0]=dv.x; d[1]=dv.y; d[2]=dv.z; d[3]=dv.w;
    }
    #pragma unroll
    for (int r = 0; r < 4; ++r)
        atomicAdd(&c_scr[nb + s[r]], dis_scr[nb + d[r]]);
}

// -------- scale: gb = bf16(g * dis) (needs gemm + dis) --------
__global__ void scale_kernel() {
    int n = blockIdx.x * blockDim.x + threadIdx.x;
    if (n >= TOT) return;
    float dd = dis_scr[n];
    const float4* gi = (const float4*)(g_scr + (size_t)n * HID);
    float4 a = gi[0], b = gi[1], c = gi[2], d = gi[3];
    uint4 o0, o1;
    o0.x = bf2pack(a.x*dd, a.y*dd);  o0.y = bf2pack(a.z*dd, a.w*dd);
    o0.z = bf2pack(b.x*dd, b.y*dd);  o0.w = bf2pack(b.z*dd, b.w*dd);
    o1.x = bf2pack(c.x*dd, c.y*dd);  o1.y = bf2pack(c.z*dd, c.w*dd);
    o1.z = bf2pack(d.x*dd, d.y*dd);  o1.w = bf2pack(d.z*dd, d.w*dd);
    uint4* go = (uint4*)(gb_scr + (size_t)n * HID);
    go[0] = o0; go[1] = o1;
}

// -------- gather: warp/node; paired lanes, bf16x2 accumulation; writes f[n] --------
__global__ void __launch_bounds__(256) gather_kernel(const float* __restrict__ b1,
                                                     const float* __restrict__ W2) {
    int wid  = threadIdx.x >> 5;
    int lane = threadIdx.x & 31;
    int n = blockIdx.x * 8 + wid;            // 100000 % 8 == 0: blocks never straddle graphs
    int gidx = blockIdx.x / (NNODE / 8);

    int cnt = cnt_scr[n];
    if (cnt > CAP) cnt = CAP;
    int start = n * CAP;
    int q2 = lane & 1;                       // row half (16B = 8 dims)
    int es = lane >> 1;                      // edge slot 0..15

    const uint4* gbp = (const uint4*)gb_scr; // row = 2 × uint4

    __nv_bfloat162 acc0, acc1, acc2, acc3;
    {
        __nv_bfloat162 z = __float2bfloat162_rn(0.f);
        acc0 = z; acc1 = z; acc2 = z; acc3 = z;
    }

    for (int i = es; i < cnt; i += 16) {
        int s = bucket_scr[start + i];
        uint4 v = gbp[s * 2 + q2];
        acc0 = __hadd2(acc0, *(__nv_bfloat162*)&v.x);
        acc1 = __hadd2(acc1, *(__nv_bfloat162*)&v.y);
        acc2 = __hadd2(acc2, *(__nv_bfloat162*)&v.z);
        acc3 = __hadd2(acc3, *(__nv_bfloat162*)&v.w);
    }

    #pragma unroll
    for (int off = 16; off >= 2; off >>= 1) {
        acc0 = __hadd2(acc0, shfl_down_bf2(acc0, off));
        acc1 = __hadd2(acc1, shfl_down_bf2(acc1, off));
        acc2 = __hadd2(acc2, shfl_down_bf2(acc2, off));
        acc3 = __hadd2(acc3, shfl_down_bf2(acc3, off));
    }

    float dd = dis_scr[n];
    float zp = 0.f;
    if (lane < 2) {
        float fa[8];
        { float2 t;
          t = __bfloat1622float2(acc0); fa[0]=t.x; fa[1]=t.y;
          t = __bfloat1622float2(acc1); fa[2]=t.x; fa[3]=t.y;
          t = __bfloat1622float2(acc2); fa[4]=t.x; fa[5]=t.y;
          t = __bfloat1622float2(acc3); fa[6]=t.x; fa[7]=t.y; }
        uint4 gv = gbp[n * 2 + q2];
        float2 g0 = __bfloat1622float2(*(__nv_bfloat162*)&gv.x);
        float2 g1 = __bfloat1622float2(*(__nv_bfloat162*)&gv.y);
        float2 g2 = __bfloat1622float2(*(__nv_bfloat162*)&gv.z);
        float2 g3 = __bfloat1622float2(*(__nv_bfloat162*)&gv.w);
        float gg[8] = {g0.x,g0.y,g1.x,g1.y,g2.x,g2.y,g3.x,g3.y};
        float4 bbA = __ldg((const float4*)b1 + q2 * 2);
        float4 bbB = __ldg((const float4*)b1 + q2 * 2 + 1);
        float4 wwA = __ldg((const float4*)W2 + q2 * 2);
        float4 wwB = __ldg((const float4*)W2 + q2 * 2 + 1);
        float bb[8] = {bbA.x,bbA.y,bbA.z,bbA.w,bbB.x,bbB.y,bbB.z,bbB.w};
        float ww[8] = {wwA.x,wwA.y,wwA.z,wwA.w,wwB.x,wwB.y,wwB.z,wwB.w};
        #pragma unroll
        for (int i = 0; i < 8; ++i) {
            float h = fmaxf(fmaf(dd, fa[i] + gg[i], bb[i]), 0.f);
            zp = fmaf(h, ww[i], zp);
        }
    }
    zp += __shfl_xor_sync(0xffffffffu, zp, 1);   // lane0 = full dot

    __shared__ float part[8];
    if (lane == 0) {
        float f = zp * dd;                   // f[n] = z[n]*dis[n]
        f_scr[n] = f;
        part[wid] = f * dd;                  // self-loop term f[n]*dis[n]
    }
    __syncthreads();
    if (threadIdx.x == 0) {
        float t = 0.f;
        #pragma unroll
        for (int w = 0; w < 8; ++w) t += part[w];
        atomicAdd(&score_scr[gidx], t);
    }
}

// -------- dot: score[g] += sum_n f[n]*c[n]  (edge term via src-grouped dual) --------
__global__ void __launch_bounds__(256) dot_kernel() {
    int idx = blockIdx.x * 256 + threadIdx.x;
    int gy = blockIdx.y;
    float v = 0.f;
    if (idx < NNODE) {
        int n = gy * NNODE + idx;
        v = f_scr[n] * c_scr[n];
    }
    #pragma unroll
    for (int off = 16; off; off >>= 1)
        v += __shfl_down_sync(0xffffffffu, v, off);
    __shared__ float part[8];
    if ((threadIdx.x & 31) == 0) part[threadIdx.x >> 5] = v;
    __syncthreads();
    if (threadIdx.x == 0) {
        float t = 0.f;
        #pragma unroll
        for (int w = 0; w < 8; ++w) t += part[w];
        atomicAdd(&score_scr[gy], t);
    }
}

// -------- softmax over 5 graph scores --------
__global__ void softmax_kernel(const float* __restrict__ b2, float* __restrict__ out) {
    if (threadIdx.x == 0) {
        float s[NG], m = -1e30f;
        for (int g = 0; g < NG; ++g) {
            s[g] = score_scr[g] * (1.0f / (float)NNODE) + b2[0];
            m = fmaxf(m, s[g]);
        }
        float sum = 0.f, e[NG];
        for (int g = 0; g < NG; ++g) { e[g] = expf(s[g] - m); sum += e[g]; }
        for (int g = 0; g < NG; ++g) out[g] = e[g] / sum;
    }
}

extern "C" void kernel_launch(void* const* d_in, const int* in_sizes, int n_in,
                              void* d_out, int out_size) {
    const float* emb = (const float*)d_in[0];
    const void*  ei  = d_in[1];
    const float* W1  = (const float*)d_in[2];
    const float* b1  = (const float*)d_in[3];
    const float* W2  = (const float*)d_in[4];
    const float* b2  = (const float*)d_in[5];
    float* out = (float*)d_out;

    // one-time host-side resources (no device allocations)
    static cudaStream_t side = nullptr;
    static cudaEvent_t evFork = nullptr, evDis = nullptr, evGather = nullptr;
    static void *cntAddr = nullptr, *scoreAddr = nullptr, *cAddr = nullptr;
    if (!side) {
        cudaStreamCreateWithFlags(&side, cudaStreamNonBlocking);
        cudaEventCreateWithFlags(&evFork, cudaEventDisableTiming);
        cudaEventCreateWithFlags(&evDis, cudaEventDisableTiming);
        cudaEventCreateWithFlags(&evGather, cudaEventDisableTiming);
        cudaGetSymbolAddress(&cntAddr, cnt_scr);
        cudaGetSymbolAddress(&scoreAddr, score_scr);
        cudaGetSymbolAddress(&cAddr, c_scr);
        cudaFuncSetAttribute((const void*)gemm_kernel,
                             cudaFuncAttributeMaxDynamicSharedMemorySize, GEMM_SMEM);
    }

    cudaMemsetAsync(cntAddr, 0, TOT * sizeof(int), 0);
    cudaMemsetAsync(scoreAddr, 0, NG * sizeof(float), 0);
    cudaMemsetAsync(cAddr, 0, TOT * sizeof(float), 0);

    cudaEventRecord(evFork, 0);
    cudaStreamWaitEvent(side, evFork, 0);

    dim3 eg((NEDGE / 4 + 255) / 256, NG);

    fill_kernel<<<eg, 256>>>(ei);                                       // k1 main
    gemm_kernel<<<(TOT + 511) / 512, 256, GEMM_SMEM, side>>>(emb, W1);  // k2 side

    dis_kernel<<<(TOT + 255) / 256, 256>>>();                           // k3 main (after fill)
    cudaEventRecord(evDis, 0);

    c_kernel<<<eg, 256>>>(ei);                                          // k4 main <- profiled

    cudaStreamWaitEvent(side, evDis, 0);                                // side: gemm done + dis ready
    scale_kernel<<<(TOT + 255) / 256, 256, 0, side>>>();                // k5 side
    gather_kernel<<<TOT / 8, 256, 0, side>>>(b1, W2);                   // k6 side (bucket ready: after dis on main)
    cudaEventRecord(evGather, side);

    cudaStreamWaitEvent(0, evGather, 0);                                // join on main
    dim3 dg((NNODE + 255) / 256, NG);
    dot_kernel<<<dg, 256>>>();                                          // k7 main
    softmax_kernel<<<1, 32>>>(b2, out);                                 // k8 main
}

// round 10
// speedup vs baseline: 1.3829x; 1.0534x over previous
#include <cuda_runtime.h>
#include <cuda_bf16.h>

#define NNODE   100000
#define NEDGE   3200000
#define DIM     300
#define HID     16
#define NG      5
#define TOT     (NG*NNODE)      // 500000
#define TOTEDGE (NG*NEDGE)      // 16000000
#define CAP     80              // bucket slots per node; P(deg>=80)~5e-13 per node

// -------- scratch (no allocations allowed; __device__ globals) --------
__device__ __align__(16) float          g_scr[TOT*HID];   // raw emb@W1 (fp32)
__device__ __align__(16) unsigned short gb_scr[TOT*HID];  // scaled bf16 g (16MB)
__device__ int   bucket_scr[TOT*CAP];                     // 160MB: src lists by dst
__device__ int   cnt_scr[TOT];                            // in-degree
__device__ float dis_scr[TOT];
__device__ float f_scr[TOT];                              // f[n] = z[n]*dis[n]
__device__ float c_scr[TOT];                              // c[s] = sum_out dis[dst]
__device__ float score_scr[NG];

__device__ __forceinline__ unsigned bf2pack(float a, float b) {
    __nv_bfloat162 t = __float22bfloat162_rn(make_float2(a, b));
    return *(unsigned*)&t;
}
__device__ __forceinline__ __nv_bfloat162 shfl_down_bf2(__nv_bfloat162 v, int off) {
    unsigned u = __shfl_down_sync(0xffffffffu, *(unsigned*)&v, off);
    return *(__nv_bfloat162*)&u;
}

// -------- bucket fill: per-block dtype detect, one atomic per edge --------
__global__ void fill_kernel(const void* __restrict__ ei) {
    __shared__ int s64;
    if (threadIdx.x < 32) {
        const unsigned long long* p = (const unsigned long long*)ei;
        unsigned long long a = p[threadIdx.x];
        unsigned long long b = p[threadIdx.x + 32];
        int bad = ((a >> 32) | (b >> 32)) != 0ULL;   // int32 data -> high words nonzero w.h.p.
        unsigned m = __ballot_sync(0xffffffffu, bad);
        if (threadIdx.x == 0) s64 = (m == 0);
    }
    __syncthreads();
    int is64 = s64;

    int e0 = (blockIdx.x * blockDim.x + threadIdx.x) * 4;
    if (e0 >= NEDGE) return;
    int gy = blockIdx.y;
    int nb = gy * NNODE;
    int s[4], d[4];
    if (is64) {
        const long long* base = (const long long*)ei + (long long)gy * 2 * NEDGE;
        longlong2 sa = *(const longlong2*)(base + e0);
        longlong2 sb = *(const longlong2*)(base + e0 + 2);
        longlong2 da = *(const longlong2*)(base + NEDGE + e0);
        longlong2 db = *(const longlong2*)(base + NEDGE + e0 + 2);
        s[0]=(int)sa.x; s[1]=(int)sa.y; s[2]=(int)sb.x; s[3]=(int)sb.y;
        d[0]=(int)da.x; d[1]=(int)da.y; d[2]=(int)db.x; d[3]=(int)db.y;
    } else {
        const int* base = (const int*)ei + (long long)gy * 2 * NEDGE;
        int4 sv = *(const int4*)(base + e0);
        int4 dv = *(const int4*)(base + NEDGE + e0);
        s[0]=sv.x; s[1]=sv.y; s[2]=sv.z; s[3]=sv.w;
        d[0]=dv.x; d[1]=dv.y; d[2]=dv.z; d[3]=dv.w;
    }
    #pragma unroll
    for (int r = 0; r < 4; ++r) {
        int ds = nb + d[r];
        int pos = atomicAdd(&cnt_scr[ds], 1);
        if (pos < CAP) __stcs(&bucket_scr[ds * CAP + pos], nb + s[r]);  // streaming store
    }
}

// -------- GEMM (raw): g[n][k] = sum_j emb[n][j]*W1[j][k]  (scalar FMA) --------
#define JC 30
#define SA_STRIDE 513
#define SW_FLOATS (DIM*HID)          // 4800
#define SA_FLOATS (JC*SA_STRIDE)     // 15390
#define GEMM_SMEM ((SW_FLOATS + SA_FLOATS) * 4)

#define STEP(ACC, A) \
    ACC[0]=fmaf(A,w0.x,ACC[0]);  ACC[1]=fmaf(A,w0.y,ACC[1]);  \
    ACC[2]=fmaf(A,w0.z,ACC[2]);  ACC[3]=fmaf(A,w0.w,ACC[3]);  \
    ACC[4]=fmaf(A,w1.x,ACC[4]);  ACC[5]=fmaf(A,w1.y,ACC[5]);  \
    ACC[6]=fmaf(A,w1.z,ACC[6]);  ACC[7]=fmaf(A,w1.w,ACC[7]);  \
    ACC[8]=fmaf(A,w2.x,ACC[8]);  ACC[9]=fmaf(A,w2.y,ACC[9]);  \
    ACC[10]=fmaf(A,w2.z,ACC[10]);ACC[11]=fmaf(A,w2.w,ACC[11]);\
    ACC[12]=fmaf(A,w3.x,ACC[12]);ACC[13]=fmaf(A,w3.y,ACC[13]);\
    ACC[14]=fmaf(A,w3.z,ACC[14]);ACC[15]=fmaf(A,w3.w,ACC[15]);

__global__ void __launch_bounds__(256) gemm_kernel(const float* __restrict__ emb,
                                                   const float* __restrict__ W1) {
    extern __shared__ float sm[];
    float* sW = sm;                // 4800 floats
    float* sA = sm + SW_FLOATS;    // [JC][513]
    int tid = threadIdx.x;
    int nbase = blockIdx.x * 512;

    for (int idx = tid; idx < SW_FLOATS; idx += 256) sW[idx] = W1[idx];

    float acc0[16], acc1[16];
    #pragma unroll
    for (int k = 0; k < 16; ++k) { acc0[k] = 0.f; acc1[k] = 0.f; }

    for (int c = 0; c < 10; ++c) {
        int j0 = c * JC;
        __syncthreads();
        #pragma unroll
        for (int it = 0; it < 30; ++it) {
            int idx = it * 256 + tid;
            int n = idx / 15;
            int jp = idx - n * 15;
            int gn = nbase + n;
            float2 v = make_float2(0.f, 0.f);
            if (gn < TOT)
                v = *(const float2*)(emb + (size_t)gn * DIM + j0 + 2 * jp);
            sA[(2 * jp)     * SA_STRIDE + n] = v.x;
            sA[(2 * jp + 1) * SA_STRIDE + n] = v.y;
        }
        __syncthreads();
        #pragma unroll
        for (int jl = 0; jl < JC; ++jl) {
            float a0 = sA[jl * SA_STRIDE + tid];
            float a1 = sA[jl * SA_STRIDE + 256 + tid];
            const float4* wr = (const float4*)(sW + (j0 + jl) * HID);
            float4 w0 = wr[0], w1 = wr[1], w2 = wr[2], w3 = wr[3];
            STEP(acc0, a0)
            STEP(acc1, a1)
        }
    }

    int gn0 = nbase + tid;
    int gn1 = nbase + 256 + tid;
    if (gn0 < TOT) {
        float4* o = (float4*)(g_scr + (size_t)gn0 * HID);
        o[0] = make_float4(acc0[0],  acc0[1],  acc0[2],  acc0[3]);
        o[1] = make_float4(acc0[4],  acc0[5],  acc0[6],  acc0[7]);
        o[2] = make_float4(acc0[8],  acc0[9],  acc0[10], acc0[11]);
        o[3] = make_float4(acc0[12], acc0[13], acc0[14], acc0[15]);
    }
    if (gn1 < TOT) {
        float4* o = (float4*)(g_scr + (size_t)gn1 * HID);
        o[0] = make_float4(acc1[0],  acc1[1],  acc1[2],  acc1[3]);
        o[1] = make_float4(acc1[4],  acc1[5],  acc1[6],  acc1[7]);
        o[2] = make_float4(acc1[8],  acc1[9],  acc1[10], acc1[11]);
        o[3] = make_float4(acc1[12], acc1[13], acc1[14], acc1[15]);
    }
}

// -------- dis = rsqrt(deg+1) (needs only cnt, runs right after fill) --------
__global__ void dis_kernel() {
    int n = blockIdx.x * blockDim.x + threadIdx.x;
    if (n < TOT) dis_scr[n] = rsqrtf((float)cnt_scr[n] + 1.0f);
}

// -------- cdual: c[s] += dis[d] for each s in bucket[d]  (bucket-based, no edge re-read) --------
__global__ void __launch_bounds__(256) cdual_kernel() {
    int wid  = threadIdx.x >> 5;
    int lane = threadIdx.x & 31;
    int n = blockIdx.x * 8 + wid;            // dst node
    int cnt = cnt_scr[n];
    if (cnt > CAP) cnt = CAP;
    int start = n * CAP;
    float dd = dis_scr[n];
    for (int i = lane; i < cnt; i += 32) {
        int s = __ldcs(&bucket_scr[start + i]);
        atomicAdd(&c_scr[s], dd);            // RED (no return)
    }
}

// -------- scale: gb = bf16(g * dis) (needs gemm + dis) --------
__global__ void scale_kernel() {
    int n = blockIdx.x * blockDim.x + threadIdx.x;
    if (n >= TOT) return;
    float dd = dis_scr[n];
    const float4* gi = (const float4*)(g_scr + (size_t)n * HID);
    float4 a = gi[0], b = gi[1], c = gi[2], d = gi[3];
    uint4 o0, o1;
    o0.x = bf2pack(a.x*dd, a.y*dd);  o0.y = bf2pack(a.z*dd, a.w*dd);
    o0.z = bf2pack(b.x*dd, b.y*dd);  o0.w = bf2pack(b.z*dd, b.w*dd);
    o1.x = bf2pack(c.x*dd, c.y*dd);  o1.y = bf2pack(c.z*dd, c.w*dd);
    o1.z = bf2pack(d.x*dd, d.y*dd);  o1.w = bf2pack(d.z*dd, d.w*dd);
    uint4* go = (uint4*)(gb_scr + (size_t)n * HID);
    go[0] = o0; go[1] = o1;
}

// -------- gather: warp/node; paired lanes, bf16x2 accumulation; writes f[n] --------
__global__ void __launch_bounds__(256) gather_kernel(const float* __restrict__ b1,
                                                     const float* __restrict__ W2) {
    int wid  = threadIdx.x >> 5;
    int lane = threadIdx.x & 31;
    int n = blockIdx.x * 8 + wid;            // 100000 % 8 == 0: blocks never straddle graphs
    int gidx = blockIdx.x / (NNODE / 8);

    int cnt = cnt_scr[n];
    if (cnt > CAP) cnt = CAP;
    int start = n * CAP;
    int q2 = lane & 1;                       // row half (16B = 8 dims)
    int es = lane >> 1;                      // edge slot 0..15

    const uint4* gbp = (const uint4*)gb_scr; // row = 2 × uint4

    __nv_bfloat162 acc0, acc1, acc2, acc3;
    {
        __nv_bfloat162 z = __float2bfloat162_rn(0.f);
        acc0 = z; acc1 = z; acc2 = z; acc3 = z;
    }

    for (int i = es; i < cnt; i += 16) {
        int s = __ldcs(&bucket_scr[start + i]);   // streamed, paired lanes share sector
        uint4 v = gbp[s * 2 + q2];
        acc0 = __hadd2(acc0, *(__nv_bfloat162*)&v.x);
        acc1 = __hadd2(acc1, *(__nv_bfloat162*)&v.y);
        acc2 = __hadd2(acc2, *(__nv_bfloat162*)&v.z);
        acc3 = __hadd2(acc3, *(__nv_bfloat162*)&v.w);
    }

    #pragma unroll
    for (int off = 16; off >= 2; off >>= 1) {
        acc0 = __hadd2(acc0, shfl_down_bf2(acc0, off));
        acc1 = __hadd2(acc1, shfl_down_bf2(acc1, off));
        acc2 = __hadd2(acc2, shfl_down_bf2(acc2, off));
        acc3 = __hadd2(acc3, shfl_down_bf2(acc3, off));
    }

    float dd = dis_scr[n];
    float zp = 0.f;
    if (lane < 2) {
        float fa[8];
        { float2 t;
          t = __bfloat1622float2(acc0); fa[0]=t.x; fa[1]=t.y;
          t = __bfloat1622float2(acc1); fa[2]=t.x; fa[3]=t.y;
          t = __bfloat1622float2(acc2); fa[4]=t.x; fa[5]=t.y;
          t = __bfloat1622float2(acc3); fa[6]=t.x; fa[7]=t.y; }
        uint4 gv = gbp[n * 2 + q2];
        float2 g0 = __bfloat1622float2(*(__nv_bfloat162*)&gv.x);
        float2 g1 = __bfloat1622float2(*(__nv_bfloat162*)&gv.y);
        float2 g2 = __bfloat1622float2(*(__nv_bfloat162*)&gv.z);
        float2 g3 = __bfloat1622float2(*(__nv_bfloat162*)&gv.w);
        float gg[8] = {g0.x,g0.y,g1.x,g1.y,g2.x,g2.y,g3.x,g3.y};
        float4 bbA = __ldg((const float4*)b1 + q2 * 2);
        float4 bbB = __ldg((const float4*)b1 + q2 * 2 + 1);
        float4 wwA = __ldg((const float4*)W2 + q2 * 2);
        float4 wwB = __ldg((const float4*)W2 + q2 * 2 + 1);
        float bb[8] = {bbA.x,bbA.y,bbA.z,bbA.w,bbB.x,bbB.y,bbB.z,bbB.w};
        float ww[8] = {wwA.x,wwA.y,wwA.z,wwA.w,wwB.x,wwB.y,wwB.z,wwB.w};
        #pragma unroll
        for (int i = 0; i < 8; ++i) {
            float h = fmaxf(fmaf(dd, fa[i] + gg[i], bb[i]), 0.f);
            zp = fmaf(h, ww[i], zp);
        }
    }
    zp += __shfl_xor_sync(0xffffffffu, zp, 1);   // lane0 = full dot

    __shared__ float part[8];
    if (lane == 0) {
        float f = zp * dd;                   // f[n] = z[n]*dis[n]
        f_scr[n] = f;
        part[wid] = f * dd;                  // self-loop term f[n]*dis[n]
    }
    __syncthreads();
    if (threadIdx.x == 0) {
        float t = 0.f;
        #pragma unroll
        for (int w = 0; w < 8; ++w) t += part[w];
        atomicAdd(&score_scr[gidx], t);
    }
}

// -------- dot: score[g] += sum_n f[n]*c[n]  (edge term via src-grouped dual) --------
__global__ void __launch_bounds__(256) dot_kernel() {
    int idx = blockIdx.x * 256 + threadIdx.x;
    int gy = blockIdx.y;
    float v = 0.f;
    if (idx < NNODE) {
        int n = gy * NNODE + idx;
        v = f_scr[n] * c_scr[n];
    }
    #pragma unroll
    for (int off = 16; off; off >>= 1)
        v += __shfl_down_sync(0xffffffffu, v, off);
    __shared__ float part[8];
    if ((threadIdx.x & 31) == 0) part[threadIdx.x >> 5] = v;
    __syncthreads();
    if (threadIdx.x == 0) {
        float t = 0.f;
        #pragma unroll
        for (int w = 0; w < 8; ++w) t += part[w];
        atomicAdd(&score_scr[gy], t);
    }
}

// -------- softmax over 5 graph scores --------
__global__ void softmax_kernel(const float* __restrict__ b2, float* __restrict__ out) {
    if (threadIdx.x == 0) {
        float s[NG], m = -1e30f;
        for (int g = 0; g < NG; ++g) {
            s[g] = score_scr[g] * (1.0f / (float)NNODE) + b2[0];
            m = fmaxf(m, s[g]);
        }
        float sum = 0.f, e[NG];
        for (int g = 0; g < NG; ++g) { e[g] = expf(s[g] - m); sum += e[g]; }
        for (int g = 0; g < NG; ++g) out[g] = e[g] / sum;
    }
}

extern "C" void kernel_launch(void* const* d_in, const int* in_sizes, int n_in,
                              void* d_out, int out_size) {
    const float* emb = (const float*)d_in[0];
    const void*  ei  = d_in[1];
    const float* W1  = (const float*)d_in[2];
    const float* b1  = (const float*)d_in[3];
    const float* W2  = (const float*)d_in[4];
    const float* b2  = (const float*)d_in[5];
    float* out = (float*)d_out;

    // one-time host-side resources (no device allocations)
    static cudaStream_t side = nullptr;
    static cudaEvent_t evFork = nullptr, evDis = nullptr, evGather = nullptr;
    static void *cntAddr = nullptr, *scoreAddr = nullptr, *cAddr = nullptr;
    if (!side) {
        cudaStreamCreateWithFlags(&side, cudaStreamNonBlocking);
        cudaEventCreateWithFlags(&evFork, cudaEventDisableTiming);
        cudaEventCreateWithFlags(&evDis, cudaEventDisableTiming);
        cudaEventCreateWithFlags(&evGather, cudaEventDisableTiming);
        cudaGetSymbolAddress(&cntAddr, cnt_scr);
        cudaGetSymbolAddress(&scoreAddr, score_scr);
        cudaGetSymbolAddress(&cAddr, c_scr);
        cudaFuncSetAttribute((const void*)gemm_kernel,
                             cudaFuncAttributeMaxDynamicSharedMemorySize, GEMM_SMEM);
    }

    cudaMemsetAsync(cntAddr, 0, TOT * sizeof(int), 0);
    cudaMemsetAsync(scoreAddr, 0, NG * sizeof(float), 0);
    cudaMemsetAsync(cAddr, 0, TOT * sizeof(float), 0);

    cudaEventRecord(evFork, 0);
    cudaStreamWaitEvent(side, evFork, 0);

    dim3 eg((NEDGE / 4 + 255) / 256, NG);

    fill_kernel<<<eg, 256>>>(ei);                                       // k1 main
    gemm_kernel<<<(TOT + 511) / 512, 256, GEMM_SMEM, side>>>(emb, W1);  // k2 side

    dis_kernel<<<(TOT + 255) / 256, 256>>>();                           // k3 main (after fill)
    cudaEventRecord(evDis, 0);

    cdual_kernel<<<TOT / 8, 256>>>();                                   // k4 main <- profiled

    cudaStreamWaitEvent(side, evDis, 0);                                // side: gemm done + dis ready
    scale_kernel<<<(TOT + 255) / 256, 256, 0, side>>>();                // k5 side
    gather_kernel<<<TOT / 8, 256, 0, side>>>(b1, W2);                   // k6 side
    cudaEventRecord(evGather, side);

    cudaStreamWaitEvent(0, evGather, 0);                                // join on main
    dim3 dg((NNODE + 255) / 256, NG);
    dot_kernel<<<dg, 256>>>();                                          // k7 main
    softmax_kernel<<<1, 32>>>(b2, out);                                 // k8 main
}

// round 11
// speedup vs baseline: 1.4307x; 1.0346x over previous
#include <cuda_runtime.h>
#include <cuda_bf16.h>

#define NNODE   100000
#define NEDGE   3200000
#define DIM     300
#define HID     16
#define NG      5
#define TOT     (NG*NNODE)      // 500000
#define TOTEDGE (NG*NEDGE)      // 16000000
#define CAP     80              // bucket slots per node; P(deg>=80)~5e-13 per node

// -------- scratch (no allocations allowed; __device__ globals) --------
__device__ __align__(16) float          g_scr[TOT*HID];   // raw emb@W1 (fp32)
__device__ __align__(16) unsigned short gb_scr[TOT*HID];  // scaled bf16 g (16MB)
__device__ int   bucket_scr[TOT*CAP];                     // 160MB: src lists by dst
__device__ int   cnt_scr[TOT];                            // in-degree
__device__ float dis_scr[TOT];
__device__ float f_scr[TOT];                              // f[n] = z[n]*dis[n]
__device__ float c_scr[TOT];                              // c[s] = sum_out dis[dst]
__device__ float score_scr[NG];

__device__ __forceinline__ unsigned bf2pack(float a, float b) {
    __nv_bfloat162 t = __float22bfloat162_rn(make_float2(a, b));
    return *(unsigned*)&t;
}
__device__ __forceinline__ __nv_bfloat162 shfl_down_bf2(__nv_bfloat162 v, int off) {
    unsigned u = __shfl_down_sync(0xffffffffu, *(unsigned*)&v, off);
    return *(__nv_bfloat162*)&u;
}

// -------- bucket fill: per-block dtype detect, one atomic per edge --------
__global__ void fill_kernel(const void* __restrict__ ei) {
    __shared__ int s64;
    if (threadIdx.x < 32) {
        const unsigned long long* p = (const unsigned long long*)ei;
        unsigned long long a = p[threadIdx.x];
        unsigned long long b = p[threadIdx.x + 32];
        int bad = ((a >> 32) | (b >> 32)) != 0ULL;   // int32 data -> high words nonzero w.h.p.
        unsigned m = __ballot_sync(0xffffffffu, bad);
        if (threadIdx.x == 0) s64 = (m == 0);
    }
    __syncthreads();
    int is64 = s64;

    int e0 = (blockIdx.x * blockDim.x + threadIdx.x) * 4;
    if (e0 >= NEDGE) return;
    int gy = blockIdx.y;
    int nb = gy * NNODE;
    int s[4], d[4];
    if (is64) {
        const long long* base = (const long long*)ei + (long long)gy * 2 * NEDGE;
        longlong2 sa = *(const longlong2*)(base + e0);
        longlong2 sb = *(const longlong2*)(base + e0 + 2);
        longlong2 da = *(const longlong2*)(base + NEDGE + e0);
        longlong2 db = *(const longlong2*)(base + NEDGE + e0 + 2);
        s[0]=(int)sa.x; s[1]=(int)sa.y; s[2]=(int)sb.x; s[3]=(int)sb.y;
        d[0]=(int)da.x; d[1]=(int)da.y; d[2]=(int)db.x; d[3]=(int)db.y;
    } else {
        const int* base = (const int*)ei + (long long)gy * 2 * NEDGE;
        int4 sv = *(const int4*)(base + e0);
        int4 dv = *(const int4*)(base + NEDGE + e0);
        s[0]=sv.x; s[1]=sv.y; s[2]=sv.z; s[3]=sv.w;
        d[0]=dv.x; d[1]=dv.y; d[2]=dv.z; d[3]=dv.w;
    }
    #pragma unroll
    for (int r = 0; r < 4; ++r) {
        int ds = nb + d[r];
        int pos = atomicAdd(&cnt_scr[ds], 1);
        if (pos < CAP) __stcs(&bucket_scr[ds * CAP + pos], nb + s[r]);  // streaming store
    }
}

// -------- GEMM (raw): g[n][k] = sum_j emb[n][j]*W1[j][k]  (scalar FMA) --------
#define JC 30
#define SA_STRIDE 513
#define SW_FLOATS (DIM*HID)          // 4800
#define SA_FLOATS (JC*SA_STRIDE)     // 15390
#define GEMM_SMEM ((SW_FLOATS + SA_FLOATS) * 4)

#define STEP(ACC, A) \
    ACC[0]=fmaf(A,w0.x,ACC[0]);  ACC[1]=fmaf(A,w0.y,ACC[1]);  \
    ACC[2]=fmaf(A,w0.z,ACC[2]);  ACC[3]=fmaf(A,w0.w,ACC[3]);  \
    ACC[4]=fmaf(A,w1.x,ACC[4]);  ACC[5]=fmaf(A,w1.y,ACC[5]);  \
    ACC[6]=fmaf(A,w1.z,ACC[6]);  ACC[7]=fmaf(A,w1.w,ACC[7]);  \
    ACC[8]=fmaf(A,w2.x,ACC[8]);  ACC[9]=fmaf(A,w2.y,ACC[9]);  \
    ACC[10]=fmaf(A,w2.z,ACC[10]);ACC[11]=fmaf(A,w2.w,ACC[11]);\
    ACC[12]=fmaf(A,w3.x,ACC[12]);ACC[13]=fmaf(A,w3.y,ACC[13]);\
    ACC[14]=fmaf(A,w3.z,ACC[14]);ACC[15]=fmaf(A,w3.w,ACC[15]);

__global__ void __launch_bounds__(256) gemm_kernel(const float* __restrict__ emb,
                                                   const float* __restrict__ W1) {
    extern __shared__ float sm[];
    float* sW = sm;                // 4800 floats
    float* sA = sm + SW_FLOATS;    // [JC][513]
    int tid = threadIdx.x;
    int nbase = blockIdx.x * 512;

    for (int idx = tid; idx < SW_FLOATS; idx += 256) sW[idx] = W1[idx];

    float acc0[16], acc1[16];
    #pragma unroll
    for (int k = 0; k < 16; ++k) { acc0[k] = 0.f; acc1[k] = 0.f; }

    for (int c = 0; c < 10; ++c) {
        int j0 = c * JC;
        __syncthreads();
        #pragma unroll
        for (int it = 0; it < 30; ++it) {
            int idx = it * 256 + tid;
            int n = idx / 15;
            int jp = idx - n * 15;
            int gn = nbase + n;
            float2 v = make_float2(0.f, 0.f);
            if (gn < TOT)
                v = *(const float2*)(emb + (size_t)gn * DIM + j0 + 2 * jp);
            sA[(2 * jp)     * SA_STRIDE + n] = v.x;
            sA[(2 * jp + 1) * SA_STRIDE + n] = v.y;
        }
        __syncthreads();
        #pragma unroll
        for (int jl = 0; jl < JC; ++jl) {
            float a0 = sA[jl * SA_STRIDE + tid];
            float a1 = sA[jl * SA_STRIDE + 256 + tid];
            const float4* wr = (const float4*)(sW + (j0 + jl) * HID);
            float4 w0 = wr[0], w1 = wr[1], w2 = wr[2], w3 = wr[3];
            STEP(acc0, a0)
            STEP(acc1, a1)
        }
    }

    int gn0 = nbase + tid;
    int gn1 = nbase + 256 + tid;
    if (gn0 < TOT) {
        float4* o = (float4*)(g_scr + (size_t)gn0 * HID);
        o[0] = make_float4(acc0[0],  acc0[1],  acc0[2],  acc0[3]);
        o[1] = make_float4(acc0[4],  acc0[5],  acc0[6],  acc0[7]);
        o[2] = make_float4(acc0[8],  acc0[9],  acc0[10], acc0[11]);
        o[3] = make_float4(acc0[12], acc0[13], acc0[14], acc0[15]);
    }
    if (gn1 < TOT) {
        float4* o = (float4*)(g_scr + (size_t)gn1 * HID);
        o[0] = make_float4(acc1[0],  acc1[1],  acc1[2],  acc1[3]);
        o[1] = make_float4(acc1[4],  acc1[5],  acc1[6],  acc1[7]);
        o[2] = make_float4(acc1[8],  acc1[9],  acc1[10], acc1[11]);
        o[3] = make_float4(acc1[12], acc1[13], acc1[14], acc1[15]);
    }
}

// -------- fused: dis = rsqrt(deg+1); gb = bf16(g * dis) (thread per node) --------
__global__ void disscale_kernel() {
    int n = blockIdx.x * blockDim.x + threadIdx.x;
    if (n >= TOT) return;
    float dd = rsqrtf((float)cnt_scr[n] + 1.0f);
    dis_scr[n] = dd;
    const float4* gi = (const float4*)(g_scr + (size_t)n * HID);
    float4 a = gi[0], b = gi[1], c = gi[2], d = gi[3];
    uint4 o0, o1;
    o0.x = bf2pack(a.x*dd, a.y*dd);  o0.y = bf2pack(a.z*dd, a.w*dd);
    o0.z = bf2pack(b.x*dd, b.y*dd);  o0.w = bf2pack(b.z*dd, b.w*dd);
    o1.x = bf2pack(c.x*dd, c.y*dd);  o1.y = bf2pack(c.z*dd, c.w*dd);
    o1.z = bf2pack(d.x*dd, d.y*dd);  o1.w = bf2pack(d.z*dd, d.w*dd);
    uint4* go = (uint4*)(gb_scr + (size_t)n * HID);
    go[0] = o0; go[1] = o1;
}

// -------- gatherC: one bucket walk does BOTH the row-gather and c[s] += dis[n] --------
// warp per node; paired lanes per edge (LDG.128 row halves); even lane issues the RED.
__global__ void __launch_bounds__(256) gatherc_kernel(const float* __restrict__ b1,
                                                      const float* __restrict__ W2) {
    int wid  = threadIdx.x >> 5;
    int lane = threadIdx.x & 31;
    int n = blockIdx.x * 8 + wid;            // 100000 % 8 == 0: blocks never straddle graphs
    int gidx = blockIdx.x / (NNODE / 8);

    int cnt = cnt_scr[n];
    if (cnt > CAP) cnt = CAP;
    int start = n * CAP;
    int q2 = lane & 1;                       // row half (16B = 8 dims)
    int es = lane >> 1;                      // edge slot 0..15

    const uint4* gbp = (const uint4*)gb_scr; // row = 2 × uint4
    float dd = dis_scr[n];

    __nv_bfloat162 acc0, acc1, acc2, acc3;
    {
        __nv_bfloat162 z = __float2bfloat162_rn(0.f);
        acc0 = z; acc1 = z; acc2 = z; acc3 = z;
    }

    for (int i = es; i < cnt; i += 16) {
        int s = __ldcs(&bucket_scr[start + i]);   // paired lanes share sector
        if (q2 == 0) atomicAdd(&c_scr[s], dd);    // RED, one lane per edge
        uint4 v = gbp[s * 2 + q2];
        acc0 = __hadd2(acc0, *(__nv_bfloat162*)&v.x);
        acc1 = __hadd2(acc1, *(__nv_bfloat162*)&v.y);
        acc2 = __hadd2(acc2, *(__nv_bfloat162*)&v.z);
        acc3 = __hadd2(acc3, *(__nv_bfloat162*)&v.w);
    }

    #pragma unroll
    for (int off = 16; off >= 2; off >>= 1) {
        acc0 = __hadd2(acc0, shfl_down_bf2(acc0, off));
        acc1 = __hadd2(acc1, shfl_down_bf2(acc1, off));
        acc2 = __hadd2(acc2, shfl_down_bf2(acc2, off));
        acc3 = __hadd2(acc3, shfl_down_bf2(acc3, off));
    }

    float zp = 0.f;
    if (lane < 2) {
        float fa[8];
        { float2 t;
          t = __bfloat1622float2(acc0); fa[0]=t.x; fa[1]=t.y;
          t = __bfloat1622float2(acc1); fa[2]=t.x; fa[3]=t.y;
          t = __bfloat1622float2(acc2); fa[4]=t.x; fa[5]=t.y;
          t = __bfloat1622float2(acc3); fa[6]=t.x; fa[7]=t.y; }
        uint4 gv = gbp[n * 2 + q2];
        float2 g0 = __bfloat1622float2(*(__nv_bfloat162*)&gv.x);
        float2 g1 = __bfloat1622float2(*(__nv_bfloat162*)&gv.y);
        float2 g2 = __bfloat1622float2(*(__nv_bfloat162*)&gv.z);
        float2 g3 = __bfloat1622float2(*(__nv_bfloat162*)&gv.w);
        float gg[8] = {g0.x,g0.y,g1.x,g1.y,g2.x,g2.y,g3.x,g3.y};
        float4 bbA = __ldg((const float4*)b1 + q2 * 2);
        float4 bbB = __ldg((const float4*)b1 + q2 * 2 + 1);
        float4 wwA = __ldg((const float4*)W2 + q2 * 2);
        float4 wwB = __ldg((const float4*)W2 + q2 * 2 + 1);
        float bb[8] = {bbA.x,bbA.y,bbA.z,bbA.w,bbB.x,bbB.y,bbB.z,bbB.w};
        float ww[8] = {wwA.x,wwA.y,wwA.z,wwA.w,wwB.x,wwB.y,wwB.z,wwB.w};
        #pragma unroll
        for (int i = 0; i < 8; ++i) {
            float h = fmaxf(fmaf(dd, fa[i] + gg[i], bb[i]), 0.f);
            zp = fmaf(h, ww[i], zp);
        }
    }
    zp += __shfl_xor_sync(0xffffffffu, zp, 1);   // lane0 = full dot

    __shared__ float part[8];
    if (lane == 0) {
        float f = zp * dd;                   // f[n] = z[n]*dis[n]
        f_scr[n] = f;
        part[wid] = f * dd;                  // self-loop term f[n]*dis[n]
    }
    __syncthreads();
    if (threadIdx.x == 0) {
        float t = 0.f;
        #pragma unroll
        for (int w = 0; w < 8; ++w) t += part[w];
        atomicAdd(&score_scr[gidx], t);
    }
}

// -------- dot: score[g] += sum_n f[n]*c[n]  (edge term via src-grouped dual) --------
__global__ void __launch_bounds__(256) dot_kernel() {
    int idx = blockIdx.x * 256 + threadIdx.x;
    int gy = blockIdx.y;
    float v = 0.f;
    if (idx < NNODE) {
        int n = gy * NNODE + idx;
        v = f_scr[n] * c_scr[n];
    }
    #pragma unroll
    for (int off = 16; off; off >>= 1)
        v += __shfl_down_sync(0xffffffffu, v, off);
    __shared__ float part[8];
    if ((threadIdx.x & 31) == 0) part[threadIdx.x >> 5] = v;
    __syncthreads();
    if (threadIdx.x == 0) {
        float t = 0.f;
        #pragma unroll
        for (int w = 0; w < 8; ++w) t += part[w];
        atomicAdd(&score_scr[gy], t);
    }
}

// -------- softmax over 5 graph scores --------
__global__ void softmax_kernel(const float* __restrict__ b2, float* __restrict__ out) {
    if (threadIdx.x == 0) {
        float s[NG], m = -1e30f;
        for (int g = 0; g < NG; ++g) {
            s[g] = score_scr[g] * (1.0f / (float)NNODE) + b2[0];
            m = fmaxf(m, s[g]);
        }
        float sum = 0.f, e[NG];
        for (int g = 0; g < NG; ++g) { e[g] = expf(s[g] - m); sum += e[g]; }
        for (int g = 0; g < NG; ++g) out[g] = e[g] / sum;
    }
}

extern "C" void kernel_launch(void* const* d_in, const int* in_sizes, int n_in,
                              void* d_out, int out_size) {
    const float* emb = (const float*)d_in[0];
    const void*  ei  = d_in[1];
    const float* W1  = (const float*)d_in[2];
    const float* b1  = (const float*)d_in[3];
    const float* W2  = (const float*)d_in[4];
    const float* b2  = (const float*)d_in[5];
    float* out = (float*)d_out;

    // one-time host-side resources (no device allocations)
    static cudaStream_t side = nullptr;
    static cudaEvent_t evFork = nullptr, evFill = nullptr, evTail = nullptr;
    static void *cntAddr = nullptr, *scoreAddr = nullptr, *cAddr = nullptr;
    if (!side) {
        cudaStreamCreateWithFlags(&side, cudaStreamNonBlocking);
        cudaEventCreateWithFlags(&evFork, cudaEventDisableTiming);
        cudaEventCreateWithFlags(&evFill, cudaEventDisableTiming);
        cudaEventCreateWithFlags(&evTail, cudaEventDisableTiming);
        cudaGetSymbolAddress(&cntAddr, cnt_scr);
        cudaGetSymbolAddress(&scoreAddr, score_scr);
        cudaGetSymbolAddress(&cAddr, c_scr);
        cudaFuncSetAttribute((const void*)gemm_kernel,
                             cudaFuncAttributeMaxDynamicSharedMemorySize, GEMM_SMEM);
    }

    cudaMemsetAsync(cntAddr, 0, TOT * sizeof(int), 0);
    cudaMemsetAsync(scoreAddr, 0, NG * sizeof(float), 0);
    cudaMemsetAsync(cAddr, 0, TOT * sizeof(float), 0);

    cudaEventRecord(evFork, 0);
    cudaStreamWaitEvent(side, evFork, 0);

    dim3 eg((NEDGE / 4 + 255) / 256, NG);

    fill_kernel<<<eg, 256>>>(ei);                                       // k1 main
    cudaEventRecord(evFill, 0);

    gemm_kernel<<<(TOT + 511) / 512, 256, GEMM_SMEM, side>>>(emb, W1);  // k2 side (∥ fill)

    cudaStreamWaitEvent(side, evFill, 0);                               // side now has fill+gemm done
    disscale_kernel<<<(TOT + 255) / 256, 256, 0, side>>>();             // k3 side
    gatherc_kernel<<<TOT / 8, 256, 0, side>>>(b1, W2);                  // k4 side <- profiled
    cudaEventRecord(evTail, side);

    cudaStreamWaitEvent(0, evTail, 0);                                  // join on main
    dim3 dg((NNODE + 255) / 256, NG);
    dot_kernel<<<dg, 256>>>();                                          // k5 main
    softmax_kernel<<<1, 32>>>(b2, out);                                 // k6 main
}